// round 14
// baseline (speedup 1.0000x reference)
#include <cuda_runtime.h>
#include <cuda_bf16.h>
#include <cuda_fp16.h>
#include <cstdint>

// Problem constants
#define BB 2
#define TT 2048
#define CC 2048
#define NH 16
#define DH 128
#define BT (BB * TT)        // 4096
#define NQKV (3 * CC)       // 6144
#define KDIM 2048
#define TM 128
#define TN 256
#define MTILES 2            // m-tiles per CTA (TMEM double-buffered)

// KC=32 blocking (SW64) for the projection GEMMs
#define KC2 32
#define NKC2 (KDIM / KC2)   // 64
#define ABLK 8192           // 128*32*2 bytes
#define BBLK 16384          // 256*32*2 bytes
#define STG (2 * ABLK + 2 * BBLK)   // 49152
#define NSTAGE 4

#if defined(__CUDA_ARCH_FEAT_SM103_ALL) || defined(__CUDA_ARCH_FEAT_SM100_ALL) || defined(__CUDA_ARCH_FEAT_SM101_ALL)
#define USE_TCGEN05 1
#else
#define USE_TCGEN05 0
#endif

// ---------------------------------------------------------------------------
// Scratch (device globals; allocation is forbidden)
// ---------------------------------------------------------------------------
__device__ __align__(128) __nv_bfloat16 gA_hi[BT * KDIM];
__device__ __align__(128) __nv_bfloat16 gA_lo[BT * KDIM];
__device__ __align__(128) __nv_bfloat16 gAO_hi[BT * KDIM];
__device__ __align__(128) __nv_bfloat16 gAO_lo[BT * KDIM];
__device__ __align__(128) __nv_bfloat16 gBq_hi[KDIM * NQKV];
__device__ __align__(128) __nv_bfloat16 gBq_lo[KDIM * NQKV];
__device__ __align__(128) __nv_bfloat16 gBo_hi[KDIM * CC];
__device__ __align__(128) __nv_bfloat16 gBo_lo[KDIM * CC];

// SW128 128x128 fp16 hi/lo attention tiles (32KB each tile)
__device__ __align__(128) __half gQh[BB * NH * TT * DH];
__device__ __align__(128) __half gQl[BB * NH * TT * DH];
__device__ __align__(128) __half gKh[BB * NH * TT * DH];
__device__ __align__(128) __half gKl[BB * NH * TT * DH];
__device__ __align__(128) __half gVh[BB * NH * TT * DH];   // V^T tiles
__device__ __align__(128) __half gVl[BB * NH * TT * DH];

// ---------------------------------------------------------------------------
// Helpers
// ---------------------------------------------------------------------------
#define SWZ128(o) ((o) ^ (((o) >> 3) & 0x70))
#define SWZ64(o)  ((o) ^ (((o) >> 3) & 0x30))

__device__ __forceinline__ uint32_t smem_u32(const void* p) {
    uint32_t a;
    asm("{ .reg .u64 t; cvta.to.shared.u64 t, %1; cvt.u32.u64 %0, t; }" : "=r"(a) : "l"(p));
    return a;
}

#if USE_TCGEN05
static constexpr uint64_t DESCB_SW128 =
    (uint64_t(2) << 61) | (uint64_t(1) << 46) | (uint64_t(64) << 32) | (uint64_t(1) << 16);
static constexpr uint64_t DESCB_SW64 =
    (uint64_t(4) << 61) | (uint64_t(1) << 46) | (uint64_t(32) << 32) | (uint64_t(1) << 16);
#define MAKE_DESC128(a) (DESCB_SW128 | ((uint64_t)((a) >> 4) & 0x3FFF))
#define MAKE_DESC64(a)  (DESCB_SW64  | ((uint64_t)((a) >> 4) & 0x3FFF))

__device__ __forceinline__ uint32_t elect1() {
    uint32_t p;
    asm volatile("{\n\t.reg .pred p;\n\telect.sync _|p, 0xFFFFFFFF;\n\tselp.b32 %0, 1, 0, p;\n\t}" : "=r"(p));
    return p;
}
__device__ __forceinline__ void mbar_init(uint32_t a, uint32_t c) {
    asm volatile("mbarrier.init.shared.b64 [%0], %1;" :: "r"(a), "r"(c) : "memory");
}
__device__ __forceinline__ void mbar_expect(uint32_t a, uint32_t tx) {
    asm volatile("mbarrier.arrive.expect_tx.shared.b64 _, [%0], %1;" :: "r"(a), "r"(tx) : "memory");
}
__device__ __forceinline__ void mbar_arrive(uint32_t a) {
    asm volatile("mbarrier.arrive.release.cta.shared.b64 _, [%0];" :: "r"(a) : "memory");
}
__device__ __forceinline__ void mbar_wait_acq(uint32_t a, uint32_t ph) {
    asm volatile(
        "{\n\t.reg .pred P;\n"
        "WL_%=:\n\t"
        "mbarrier.try_wait.parity.acquire.cta.shared::cta.b64 P, [%0], %1, 0x989680;\n\t"
        "@P bra WD_%=;\n\t"
        "bra WL_%=;\n"
        "WD_%=:\n\t}"
        :: "r"(a), "r"(ph) : "memory");
}
__device__ __forceinline__ void mbar_wait_rlx(uint32_t a, uint32_t ph) {
    asm volatile(
        "{\n\t.reg .pred P;\n"
        "WL_%=:\n\t"
        "mbarrier.try_wait.parity.relaxed.cta.shared::cta.b64 P, [%0], %1, 0x989680;\n\t"
        "@P bra WD_%=;\n\t"
        "bra WL_%=;\n"
        "WD_%=:\n\t}"
        :: "r"(a), "r"(ph) : "memory");
}
__device__ __forceinline__ void bulk_g2s(uint32_t dst, const void* src, uint32_t n, uint32_t mbar) {
    asm volatile(
        "cp.async.bulk.shared::cta.global.mbarrier::complete_tx::bytes [%0], [%1], %2, [%3];"
        :: "r"(dst), "l"(src), "r"(n), "r"(mbar) : "memory");
}
__device__ __forceinline__ void tc_alloc(uint32_t smem_res, uint32_t ncols) {
    asm volatile("tcgen05.alloc.cta_group::1.sync.aligned.shared::cta.b32 [%0], %1;"
                 :: "r"(smem_res), "r"(ncols) : "memory");
}
__device__ __forceinline__ void tc_dealloc(uint32_t tmem, uint32_t ncols) {
    asm volatile("tcgen05.dealloc.cta_group::1.sync.aligned.b32 %0, %1;" :: "r"(tmem), "r"(ncols));
}
__device__ __forceinline__ void tc_relinq() {
    asm volatile("tcgen05.relinquish_alloc_permit.cta_group::1.sync.aligned;");
}
__device__ __forceinline__ void tc_commit(uint32_t mbar) {
    asm volatile("tcgen05.commit.cta_group::1.mbarrier::arrive::one.shared::cluster.b64 [%0];"
                 :: "r"(mbar) : "memory");
}
__device__ __forceinline__ void tc_fence_before() {
    asm volatile("tcgen05.fence::before_thread_sync;" ::: "memory");
}
__device__ __forceinline__ void tc_fence_after() {
    asm volatile("tcgen05.fence::after_thread_sync;" ::: "memory");
}
__device__ __forceinline__ void tc_wait_ld() {
    asm volatile("tcgen05.wait::ld.sync.aligned;" ::: "memory");
}
__device__ __forceinline__ void tc_wait_st() {
    asm volatile("tcgen05.wait::st.sync.aligned;" ::: "memory");
}
__device__ __forceinline__ void mma_f16_ss(uint32_t d, uint64_t a, uint64_t b, uint32_t idesc, uint32_t en) {
    asm volatile(
        "{\n\t.reg .pred p;\n\t"
        "setp.ne.u32 p, %5, 0;\n\t"
        "tcgen05.mma.cta_group::1.kind::f16 [%0], %1, %2, %3, {%4, %4, %4, %4}, p;\n\t}"
        :: "r"(d), "l"(a), "l"(b), "r"(idesc), "r"(0u), "r"(en) : "memory");
}
__device__ __forceinline__ void mma_f16_ts(uint32_t d, uint32_t a, uint64_t b, uint32_t idesc, uint32_t en) {
    asm volatile(
        "{\n\t.reg .pred p;\n\t"
        "setp.ne.u32 p, %5, 0;\n\t"
        "tcgen05.mma.cta_group::1.kind::f16 [%0], [%1], %2, %3, {%4, %4, %4, %4}, p;\n\t}"
        :: "r"(d), "r"(a), "l"(b), "r"(idesc), "r"(0u), "r"(en) : "memory");
}
#define TC_LD_32X32B_X32(r, tmem_addr) \
    asm volatile( \
        "tcgen05.ld.sync.aligned.32x32b.x32.b32 " \
        "{%0, %1, %2, %3, %4, %5, %6, %7, " \
        " %8, %9, %10, %11, %12, %13, %14, %15, " \
        " %16, %17, %18, %19, %20, %21, %22, %23, " \
        " %24, %25, %26, %27, %28, %29, %30, %31}, [%32];" \
        : "=r"((r)[0]),  "=r"((r)[1]),  "=r"((r)[2]),  "=r"((r)[3]), \
          "=r"((r)[4]),  "=r"((r)[5]),  "=r"((r)[6]),  "=r"((r)[7]), \
          "=r"((r)[8]),  "=r"((r)[9]),  "=r"((r)[10]), "=r"((r)[11]), \
          "=r"((r)[12]), "=r"((r)[13]), "=r"((r)[14]), "=r"((r)[15]), \
          "=r"((r)[16]), "=r"((r)[17]), "=r"((r)[18]), "=r"((r)[19]), \
          "=r"((r)[20]), "=r"((r)[21]), "=r"((r)[22]), "=r"((r)[23]), \
          "=r"((r)[24]), "=r"((r)[25]), "=r"((r)[26]), "=r"((r)[27]), \
          "=r"((r)[28]), "=r"((r)[29]), "=r"((r)[30]), "=r"((r)[31]) \
        : "r"(tmem_addr))
#define TC_ST_32X32B_X32(tmem_addr, r) \
    asm volatile( \
        "tcgen05.st.sync.aligned.32x32b.x32.b32 [%0], " \
        "{%1, %2, %3, %4, %5, %6, %7, %8, " \
        " %9, %10, %11, %12, %13, %14, %15, %16, " \
        " %17, %18, %19, %20, %21, %22, %23, %24, " \
        " %25, %26, %27, %28, %29, %30, %31, %32};" \
        :: "r"(tmem_addr), \
           "r"((r)[0]),  "r"((r)[1]),  "r"((r)[2]),  "r"((r)[3]), \
           "r"((r)[4]),  "r"((r)[5]),  "r"((r)[6]),  "r"((r)[7]), \
           "r"((r)[8]),  "r"((r)[9]),  "r"((r)[10]), "r"((r)[11]), \
           "r"((r)[12]), "r"((r)[13]), "r"((r)[14]), "r"((r)[15]), \
           "r"((r)[16]), "r"((r)[17]), "r"((r)[18]), "r"((r)[19]), \
           "r"((r)[20]), "r"((r)[21]), "r"((r)[22]), "r"((r)[23]), \
           "r"((r)[24]), "r"((r)[25]), "r"((r)[26]), "r"((r)[27]), \
           "r"((r)[28]), "r"((r)[29]), "r"((r)[30]), "r"((r)[31]) \
        : "memory")

#define MM_IDESC ((1u<<4) | (1u<<7) | (1u<<10) | (32u<<17) | (8u<<24))
#define FA_IDESC ((1u<<4) | (16u<<17) | (8u<<24))
#endif // USE_TCGEN05

// ---------------------------------------------------------------------------
// Conversion kernels: fp32 -> SW64 KC=32-blocked bf16 hi/lo.
// ---------------------------------------------------------------------------
__global__ __launch_bounds__(256) void convA_kernel(
    const float* __restrict__ src, __nv_bfloat16* __restrict__ hi, __nv_bfloat16* __restrict__ lo)
{
    int e = blockIdx.x * 256 + threadIdx.x;
    int m = e >> 8;
    int k = (e & 255) << 3;
    float v[8];
    *(float4*)&v[0] = *(const float4*)&src[(size_t)m * KDIM + k];
    *(float4*)&v[4] = *(const float4*)&src[(size_t)m * KDIM + k + 4];
    __nv_bfloat16 hb[8], lb[8];
#pragma unroll
    for (int i = 0; i < 8; i++) {
        hb[i] = __float2bfloat16(v[i]);
        lb[i] = __float2bfloat16(v[i] - __bfloat162float(hb[i]));
    }
    int mt = m >> 7, r = m & 127, kc = k >> 5, kcol = k & 31;
    size_t blk = (size_t)(mt * NKC2 + kc) * ABLK;
    uint32_t off = SWZ64((uint32_t)(r * 64 + kcol * 2));
    *(uint4*)((char*)hi + blk + off) = *(uint4*)hb;
    *(uint4*)((char*)lo + blk + off) = *(uint4*)lb;
}

__global__ __launch_bounds__(256) void convB_kernel(
    const float* __restrict__ W, int N,
    __nv_bfloat16* __restrict__ hi, __nv_bfloat16* __restrict__ lo)
{
    int n = blockIdx.x * 256 + threadIdx.x;
    int k = blockIdx.y * 8;
    float v[8];
#pragma unroll
    for (int i = 0; i < 8; i++) v[i] = W[(size_t)(k + i) * N + n];
    __nv_bfloat16 hb[8], lb[8];
#pragma unroll
    for (int i = 0; i < 8; i++) {
        hb[i] = __float2bfloat16(v[i]);
        lb[i] = __float2bfloat16(v[i] - __bfloat162float(hb[i]));
    }
    int nt = n >> 8, nr = n & 255, kc = k >> 5, kcol = k & 31;
    size_t blk = (size_t)(nt * NKC2 + kc) * BBLK;
    uint32_t off = SWZ64((uint32_t)(nr * 64 + kcol * 2));
    *(uint4*)((char*)hi + blk + off) = *(uint4*)hb;
    *(uint4*)((char*)lo + blk + off) = *(uint4*)lb;
}

// ---------------------------------------------------------------------------
// tcgen05 GEMM v2: 2 m-tiles per CTA, TMEM double-buffered accumulators.
// 160 threads: warp 4 = producer (loads + MMA stream over 128 chunks),
// warps 0-3 = epilogue (drain buf0 while producer MMAs tile1 into buf1).
// Stage ring identical to R6 (4 x 48KB). MD[t] committed at a tile's last
// chunk gates both that tile's epilogue and that stage's reload.
// MODE 0: QKV -> fp16 hi/lo SW128 attention tiles.  MODE 1: fp32 row-major.
// ---------------------------------------------------------------------------
#define SBUF_OFF (NSTAGE * STG)
#define MM_SMEM (1024 + NSTAGE * STG + 4 * 32 * 33 * 4)

template <int MODE>
__global__ __launch_bounds__(160) void mm_kernel(
    const __nv_bfloat16* __restrict__ Ahi, const __nv_bfloat16* __restrict__ Alo,
    const __nv_bfloat16* __restrict__ Bhi, const __nv_bfloat16* __restrict__ Blo,
    float* __restrict__ Cout)
{
    extern __shared__ char smem[];
    const int tid = threadIdx.x;
    const int nt = blockIdx.x, mty = blockIdx.y;

#if USE_TCGEN05
    __shared__ __align__(8) uint64_t s_ctrl[16];
    const uint32_t TMP = smem_u32(&s_ctrl[0]);
    uint32_t ful[NSTAGE], don[NSTAGE];
#pragma unroll
    for (int s = 0; s < NSTAGE; s++) {
        ful[s] = smem_u32(&s_ctrl[1 + s]);
        don[s] = smem_u32(&s_ctrl[1 + NSTAGE + s]);
    }
    uint32_t MD[2] = { smem_u32(&s_ctrl[9]), smem_u32(&s_ctrl[10]) };

    const uint32_t sb = smem_u32(smem);
    const uint32_t ab = (sb + 1023u) & ~1023u;
    char* smA = smem + (ab - sb);
    const int wid = tid >> 5, lane = tid & 31;

    if (wid == 0) { tc_alloc(TMP, 512); tc_relinq(); }
    if (tid == 0) {
#pragma unroll
        for (int s = 0; s < NSTAGE; s++) { mbar_init(ful[s], 1); mbar_init(don[s], 1); }
        mbar_init(MD[0], 1); mbar_init(MD[1], 1);
    }
    __syncthreads();
    uint32_t tmem;
    asm volatile("ld.shared.b32 %0, [%1];" : "=r"(tmem) : "r"(TMP));

    if (wid == 4) {
        // ---------------- producer ----------------
        const uint32_t ep = elect1();
        int fph[NSTAGE], dph[NSTAGE];
#pragma unroll
        for (int s = 0; s < NSTAGE; s++) { fph[s] = 0; dph[s] = 0; }

        auto loadChunk = [&](int g, int st) {
            int t = g >> 6, kc = g & 63;
            int mt = mty * MTILES + t;
            const char* aB = (const char*)Ahi + (size_t)(mt * NKC2 + kc) * ABLK;
            const char* aL = (const char*)Alo + (size_t)(mt * NKC2 + kc) * ABLK;
            const char* bB = (const char*)Bhi + (size_t)(nt * NKC2 + kc) * BBLK;
            const char* bL = (const char*)Blo + (size_t)(nt * NKC2 + kc) * BBLK;
            uint32_t p = ab + st * STG;
            mbar_expect(ful[st], STG);
            bulk_g2s(p,                   aB, ABLK, ful[st]);
            bulk_g2s(p + ABLK,            aL, ABLK, ful[st]);
            bulk_g2s(p + 2 * ABLK,        bB, BBLK, ful[st]);
            bulk_g2s(p + 2 * ABLK + BBLK, bL, BBLK, ful[st]);
        };

        if (ep) {
#pragma unroll
            for (int s = 0; s < NSTAGE; s++) loadChunk(s, s);
        }
        const int NG = 64 * MTILES;
        for (int g = 0; g < NG; g++) {
            const int st = g & (NSTAGE - 1), kc = g & 63, buf = g >> 6;
            uint32_t sbase = ab + st * STG;
            mbar_wait_rlx(ful[st], fph[st]); fph[st] ^= 1;
            if (ep) {
                uint64_t ah = MAKE_DESC64(sbase);
                uint64_t al = MAKE_DESC64(sbase + ABLK);
                uint64_t bh = MAKE_DESC64(sbase + 2 * ABLK);
                uint64_t bl = MAKE_DESC64(sbase + 2 * ABLK + BBLK);
                uint32_t dacc = tmem + buf * 256;
#pragma unroll
                for (int ks = 0; ks < 2; ks++) {
                    uint64_t o = (uint64_t)(ks * 2);
                    uint32_t first = (kc == 0 && ks == 0) ? 0u : 1u;
                    mma_f16_ss(dacc, ah + o, bh + o, MM_IDESC, first);
                    mma_f16_ss(dacc, ah + o, bl + o, MM_IDESC, 1u);
                    mma_f16_ss(dacc, al + o, bh + o, MM_IDESC, 1u);
                }
                if (kc == 63) tc_commit(MD[buf]); else tc_commit(don[st]);
            }
            const int pv = g - 1;
            if (pv >= 0 && pv + NSTAGE < NG) {
                const int ps = pv & (NSTAGE - 1);
                if ((pv & 63) == 63) {
                    mbar_wait_rlx(MD[(pv >> 6) & 1], 0);
                } else {
                    mbar_wait_rlx(don[ps], dph[ps]); dph[ps] ^= 1;
                }
                if (ep) loadChunk(pv + NSTAGE, ps);
            }
        }
    } else {
        // ---------------- epilogue warps 0-3 ----------------
        float* sbuf = (float*)(smA + SBUF_OFF) + wid * (32 * 33);

        for (int t = 0; t < MTILES; t++) {
            mbar_wait_acq(MD[t], 0);
            tc_fence_after();
            const uint32_t tacc = tmem + t * 256;
            const int mBase = (mty * MTILES + t) * TM + wid * 32;
            const int nBase = nt * TN;

            if (MODE == 0) {
                const int b = mBase >> 11;
                const int tile = (mBase & 2047) >> 7;
                const int r0 = mBase & 127;
                const int which = nBase >> 11;
                const int h0 = (nBase & 2047) >> 7;
                const float qscale = 0.08838834764831845f;

#pragma unroll 1
                for (int ch = 0; ch < 8; ch++) {
                    uint32_t rg[32];
                    TC_LD_32X32B_X32(rg, tacc + ch * 32);
                    tc_wait_ld();
                    const int h = h0 + (ch >> 2);
                    const int d0 = (ch & 3) * 32;
                    const size_t tbase = ((size_t)(b * NH + h) * 16 + tile) * 32768;

                    if (which != 2) {
                        const float sc = (which == 0) ? qscale : 1.0f;
                        __half hb[32], lb[32];
#pragma unroll
                        for (int c = 0; c < 32; c++) {
                            float f = __uint_as_float(rg[c]) * sc;
                            __half hh = __float2half_rn(f);
                            hb[c] = hh;
                            lb[c] = __float2half_rn(f - __half2float(hh));
                        }
                        const int r = r0 + lane;
                        const int atom = (r >> 3) + (d0 >> 6) * 16;
                        const uint32_t base = (uint32_t)(atom * 1024 + (r & 7) * 128 + (d0 & 63) * 2);
                        char* dh = (char*)((which == 0) ? gQh : gKh) + tbase;
                        char* dl = (char*)((which == 0) ? gQl : gKl) + tbase;
#pragma unroll
                        for (int q = 0; q < 4; q++) {
                            uint32_t o = SWZ128(base + q * 16);
                            *(uint4*)(dh + o) = ((uint4*)hb)[q];
                            *(uint4*)(dl + o) = ((uint4*)lb)[q];
                        }
                    } else {
#pragma unroll
                        for (int c = 0; c < 32; c++) sbuf[lane * 33 + c] = __uint_as_float(rg[c]);
                        __syncwarp();
                        const int d = d0 + lane;
                        const int ac2 = wid >> 1;
                        const int ic2 = (wid & 1) * 32;
                        const int atom2 = (d >> 3) + ac2 * 16;
                        const uint32_t base2 = (uint32_t)(atom2 * 1024 + (d & 7) * 128 + ic2 * 2);
                        __half hv[32], lv[32];
#pragma unroll
                        for (int rr = 0; rr < 32; rr++) {
                            float f = sbuf[rr * 33 + lane];
                            __half hh = __float2half_rn(f);
                            hv[rr] = hh;
                            lv[rr] = __float2half_rn(f - __half2float(hh));
                        }
#pragma unroll
                        for (int q = 0; q < 4; q++) {
                            uint32_t o = SWZ128(base2 + q * 16);
                            *(uint4*)((char*)gVh + tbase + o) = ((uint4*)hv)[q];
                            *(uint4*)((char*)gVl + tbase + o) = ((uint4*)lv)[q];
                        }
                        __syncwarp();
                    }
                }
            } else {
#pragma unroll 1
                for (int ch = 0; ch < 8; ch++) {
                    uint32_t rg[32];
                    TC_LD_32X32B_X32(rg, tacc + ch * 32);
                    tc_wait_ld();
#pragma unroll
                    for (int c = 0; c < 32; c++) sbuf[lane * 33 + c] = __uint_as_float(rg[c]);
                    __syncwarp();
                    int ncol0 = nBase + ch * 32;
#pragma unroll 4
                    for (int rr = 0; rr < 32; rr++) {
                        int m = mBase + rr;
                        Cout[(size_t)m * CC + ncol0 + lane] = sbuf[rr * 33 + lane];
                    }
                    __syncwarp();
                }
            }
        }
    }
    __syncthreads();
    if (wid == 0) tc_dealloc(tmem, 512);
#endif
}

// ---------------------------------------------------------------------------
// tcgen05 flash attention v4: double-buffered S + reordered loop so the
// PV(j-1) tail overlaps LDTM + softmax + P-store (which need no PD wait).
// TMEM: S0[0..127] S1[128..255] O[256..383] Qh[384..447] Ql[448..511].
// smem: K0h K0l K1h K1l Vh Vl (6 x 32KB).
// ---------------------------------------------------------------------------
#define FTC_SMEM (1024 + 6 * 32768)

__global__ __launch_bounds__(128, 1) void flash_tc_kernel(
    const __half* __restrict__ pQh, const __half* __restrict__ pQl,
    const __half* __restrict__ pKh, const __half* __restrict__ pKl,
    const __half* __restrict__ pVh, const __half* __restrict__ pVl)
{
#if USE_TCGEN05
    extern __shared__ char smem[];
    __shared__ __align__(8) uint64_t ctrl[8];
    const uint32_t TMP = smem_u32(&ctrl[0]);
    const uint32_t QF  = smem_u32(&ctrl[1]);
    const uint32_t KB0 = smem_u32(&ctrl[2]);
    const uint32_t KB1 = smem_u32(&ctrl[3]);
    const uint32_t VF  = smem_u32(&ctrl[4]);
    const uint32_t SD0 = smem_u32(&ctrl[5]);
    const uint32_t SD1 = smem_u32(&ctrl[6]);
    const uint32_t PD  = smem_u32(&ctrl[7]);
    const uint32_t KF[2] = { KB0, KB1 };
    const uint32_t SD[2] = { SD0, SD1 };

    const int tid = threadIdx.x, wid = tid >> 5, lane = tid & 31;
    const int bh = blockIdx.y;
    const int qt = (int)gridDim.x - 1 - (int)blockIdx.x;   // long CTAs first

    const uint32_t sb = smem_u32(smem);
    const uint32_t ab = (sb + 1023u) & ~1023u;
    char* smA = smem + (ab - sb);
    const uint32_t sKh[2] = { ab, ab + 65536 };
    const uint32_t sKl[2] = { ab + 32768, ab + 98304 };
    const uint32_t sVh = ab + 131072, sVl = ab + 163840;

    if (wid == 0) { tc_alloc(TMP, 512); tc_relinq(); }
    if (tid == 0) {
        mbar_init(QF, 1); mbar_init(KB0, 1); mbar_init(KB1, 1);
        mbar_init(VF, 1); mbar_init(SD0, 1); mbar_init(SD1, 1); mbar_init(PD, 1);
    }
    __syncthreads();
    uint32_t tmem;
    asm volatile("ld.shared.b32 %0, [%1];" : "=r"(tmem) : "r"(TMP));
    const uint32_t tS[2] = { tmem, tmem + 128 };
    const uint32_t tO = tmem + 256;
    const uint32_t tQh = tmem + 384, tQl = tmem + 448;
    const uint32_t woff = (uint32_t)wid << 21;

    const size_t headBase = (size_t)bh * 16 * 16384;       // elements
    const size_t qOff = headBase + (size_t)qt * 16384;

    // ---- stage Q through the (not yet used) V buffers, then STTM to TMEM ----
    if (wid == 0 && elect1()) {
        mbar_expect(QF, 65536);
        bulk_g2s(sVh, pQh + qOff, 32768, QF);
        bulk_g2s(sVl, pQl + qOff, 32768, QF);
    }
    mbar_wait_acq(QF, 0);
    {
        const int r = wid * 32 + lane;
        const char* srcH = smA + 131072;
        const char* srcL = smA + 163840;
        uint32_t qr[32];
        const uint32_t rowOff = (uint32_t)((r >> 3) * 1024 + (r & 7) * 128);
#pragma unroll
        for (int i = 0; i < 8; i++)
            *(uint4*)&qr[i * 4] = *(const uint4*)(srcH + SWZ128(rowOff + i * 16));
        TC_ST_32X32B_X32(tQh + woff, qr);
#pragma unroll
        for (int i = 0; i < 8; i++)
            *(uint4*)&qr[i * 4] = *(const uint4*)(srcH + SWZ128(rowOff + 16384 + i * 16));
        TC_ST_32X32B_X32(tQh + woff + 32, qr);
#pragma unroll
        for (int i = 0; i < 8; i++)
            *(uint4*)&qr[i * 4] = *(const uint4*)(srcL + SWZ128(rowOff + i * 16));
        TC_ST_32X32B_X32(tQl + woff, qr);
#pragma unroll
        for (int i = 0; i < 8; i++)
            *(uint4*)&qr[i * 4] = *(const uint4*)(srcL + SWZ128(rowOff + 16384 + i * 16));
        TC_ST_32X32B_X32(tQl + woff + 32, qr);
        tc_wait_st();
    }
    tc_fence_before();
    __syncthreads();

    // ---- prologue: K0, V0, K1 loads; issue S-MMA(0) into S0 ----
    if (wid == 0 && elect1()) {
        tc_fence_after();
        mbar_expect(KF[0], 65536);
        bulk_g2s(sKh[0], pKh + headBase, 32768, KF[0]);
        bulk_g2s(sKl[0], pKl + headBase, 32768, KF[0]);
        mbar_expect(VF, 65536);
        bulk_g2s(sVh, pVh + headBase, 32768, VF);
        bulk_g2s(sVl, pVl + headBase, 32768, VF);
        if (qt >= 1) {
            mbar_expect(KF[1], 65536);
            bulk_g2s(sKh[1], pKh + headBase + 16384, 32768, KF[1]);
            bulk_g2s(sKl[1], pKl + headBase + 16384, 32768, KF[1]);
        }
        mbar_wait_rlx(KF[0], 0);
        uint64_t dKh = MAKE_DESC128(sKh[0]), dKl = MAKE_DESC128(sKl[0]);
#pragma unroll
        for (int ks = 0; ks < 8; ks++) {
            uint64_t o = (uint64_t)((ks & 3) * 2 + (ks >> 2) * 1024);
            mma_f16_ts(tS[0], tQh + ks * 8, dKh + o, FA_IDESC, ks == 0 ? 0u : 1u);
            mma_f16_ts(tS[0], tQh + ks * 8, dKl + o, FA_IDESC, 1u);
            mma_f16_ts(tS[0], tQl + ks * 8, dKh + o, FA_IDESC, 1u);
        }
        tc_commit(SD[0]);
    }

    const float NEG_INF = __int_as_float(0xff800000);
    float m = NEG_INF, l = 0.f;

    for (int j = 0; j <= qt; j++) {
        const int bs = j & 1;

        // S(j) ready -> registers
        mbar_wait_acq(SD[bs], (j >> 1) & 1);
        tc_fence_after();
        float s[128];
#pragma unroll
        for (int c4 = 0; c4 < 4; c4++)
            TC_LD_32X32B_X32(((uint32_t*)s) + c4 * 32, tS[bs] + woff + c4 * 32);
        tc_wait_ld();

        // ---- softmax immediately (independent of PD) ----
        if (j == qt) {
            int qrow = wid * 32 + lane;
#pragma unroll
            for (int c = 0; c < 128; c++)
                if (c > qrow) s[c] = NEG_INF;
        }
        float mx = m;
#pragma unroll
        for (int c = 0; c < 128; c++) mx = fmaxf(mx, s[c]);
        float alpha = __expf(m - mx);
        m = mx;
        float ls = 0.f;
#pragma unroll
        for (int c = 0; c < 128; c++) {
            float p = __expf(s[c] - mx);
            s[c] = p;
            ls += p;
        }
        l = l * alpha + ls;

        // ---- P -> fp16x2 -> tS[bs] cols 0..63 (no PD needed: PV(j-1) reads
        //      tS[bs^1], S-MMA(j+1) writes tS[bs^1]; our LDTM already done) ----
        {
            uint32_t pk[32];
#pragma unroll
            for (int c = 0; c < 32; c++) {
                __half2 h2 = __floats2half2_rn(s[2 * c], s[2 * c + 1]);
                pk[c] = *reinterpret_cast<uint32_t*>(&h2);
            }
            TC_ST_32X32B_X32(tS[bs] + woff, pk);
#pragma unroll
            for (int c = 0; c < 32; c++) {
                __half2 h2 = __floats2half2_rn(s[64 + 2 * c], s[64 + 2 * c + 1]);
                pk[c] = *reinterpret_cast<uint32_t*>(&h2);
            }
            TC_ST_32X32B_X32(tS[bs] + woff + 32, pk);
            tc_wait_st();
        }

        // ---- now require PV(j-1) done (V reuse, P(j-1) buf reuse, O rescale) ----
        if (j > 0) { mbar_wait_acq(PD, (j - 1) & 1); tc_fence_after(); }

        if (wid == 0 && elect1()) {
            if (j > 0) {            // V(j) reload
                mbar_expect(VF, 65536);
                bulk_g2s(sVh, pVh + headBase + (size_t)j * 16384, 32768, VF);
                bulk_g2s(sVl, pVl + headBase + (size_t)j * 16384, 32768, VF);
            }
            if (j + 2 <= qt) {      // K(j+2) prefetch
                mbar_expect(KF[bs], 65536);
                bulk_g2s(sKh[bs], pKh + headBase + (size_t)(j + 2) * 16384, 32768, KF[bs]);
                bulk_g2s(sKl[bs], pKl + headBase + (size_t)(j + 2) * 16384, 32768, KF[bs]);
            }
            if (j + 1 <= qt) {      // S-MMA(j+1) into the other S buffer
                mbar_wait_rlx(KF[bs ^ 1], ((j + 1) >> 1) & 1);
                uint64_t dKh = MAKE_DESC128(sKh[bs ^ 1]), dKl = MAKE_DESC128(sKl[bs ^ 1]);
#pragma unroll
                for (int ks = 0; ks < 8; ks++) {
                    uint64_t o = (uint64_t)((ks & 3) * 2 + (ks >> 2) * 1024);
                    mma_f16_ts(tS[bs ^ 1], tQh + ks * 8, dKh + o, FA_IDESC, ks == 0 ? 0u : 1u);
                    mma_f16_ts(tS[bs ^ 1], tQh + ks * 8, dKl + o, FA_IDESC, 1u);
                    mma_f16_ts(tS[bs ^ 1], tQl + ks * 8, dKh + o, FA_IDESC, 1u);
                }
                tc_commit(SD[bs ^ 1]);
            }
        }

        // ---- O rescale (needs PD; per-warp skip when all alpha==1) ----
        if (j > 0 && !__all_sync(0xffffffffu, alpha == 1.0f)) {
#pragma unroll 1
            for (int c4 = 0; c4 < 4; c4++) {
                uint32_t o[32];
                TC_LD_32X32B_X32(o, tO + woff + c4 * 32);
                tc_wait_ld();
#pragma unroll
                for (int c = 0; c < 32; c++)
                    o[c] = __float_as_uint(__uint_as_float(o[c]) * alpha);
                TC_ST_32X32B_X32(tO + woff + c4 * 32, o);
            }
            tc_wait_st();
        }
        tc_fence_before();
        __syncthreads();

        // ---- O += P * V^T (A = P in tS[bs]) ----
        if (wid == 0 && elect1()) {
            mbar_wait_rlx(VF, j & 1);
            tc_fence_after();
            uint64_t dVh = MAKE_DESC128(sVh), dVl = MAKE_DESC128(sVl);
#pragma unroll
            for (int ks = 0; ks < 8; ks++) {
                uint64_t o = (uint64_t)((ks & 3) * 2 + (ks >> 2) * 1024);
                mma_f16_ts(tO, tS[bs] + ks * 8, dVh + o, FA_IDESC, (j == 0 && ks == 0) ? 0u : 1u);
            }
#pragma unroll
            for (int ks = 0; ks < 8; ks++) {
                uint64_t o = (uint64_t)((ks & 3) * 2 + (ks >> 2) * 1024);
                mma_f16_ts(tO, tS[bs] + ks * 8, dVl + o, FA_IDESC, 1u);
            }
            tc_commit(PD);
        }
    }

    mbar_wait_acq(PD, qt & 1);
    tc_fence_after();

    // ---- epilogue: O/l -> SW64 KC=32-blocked bf16 hi/lo AO ----
    const float invl = 1.0f / l;
    const int b = bh >> 4, h = bh & 15;
    const int r = wid * 32 + lane;
    const int mt2 = b * 16 + qt;
#pragma unroll 1
    for (int ch = 0; ch < 4; ch++) {
        uint32_t o[32];
        TC_LD_32X32B_X32(o, tO + woff + ch * 32);
        tc_wait_ld();
        __nv_bfloat16 hb[32], lb[32];
#pragma unroll
        for (int c = 0; c < 32; c++) {
            float f = __uint_as_float(o[c]) * invl;
            __nv_bfloat16 hh = __float2bfloat16(f);
            hb[c] = hh;
            lb[c] = __float2bfloat16(f - __bfloat162float(hh));
        }
        const int kc = h * 4 + ch;
        const size_t blk = (size_t)(mt2 * NKC2 + kc) * ABLK;
        const uint32_t base = (uint32_t)(r * 64);
#pragma unroll
        for (int q = 0; q < 4; q++) {
            uint32_t off = SWZ64(base + q * 16);
            *(uint4*)((char*)gAO_hi + blk + off) = ((uint4*)hb)[q];
            *(uint4*)((char*)gAO_lo + blk + off) = ((uint4*)lb)[q];
        }
    }
    __syncthreads();
    if (wid == 0) tc_dealloc(tmem, 512);
#endif
}

// ---------------------------------------------------------------------------
extern "C" void kernel_launch(void* const* d_in, const int* in_sizes, int n_in,
                              void* d_out, int out_size)
{
    const float* x    = (const float*)d_in[0];
    const float* Wqkv = (const float*)d_in[2];
    const float* Wout = (const float*)d_in[3];
    float* out = (float*)d_out;

    cudaFuncSetAttribute(mm_kernel<0>, cudaFuncAttributeMaxDynamicSharedMemorySize, MM_SMEM);
    cudaFuncSetAttribute(mm_kernel<1>, cudaFuncAttributeMaxDynamicSharedMemorySize, MM_SMEM);
    cudaFuncSetAttribute(flash_tc_kernel, cudaFuncAttributeMaxDynamicSharedMemorySize, FTC_SMEM);

    __nv_bfloat16 *pAhi, *pAlo, *pAOhi, *pAOlo, *pBqhi, *pBqlo, *pBohi, *pBolo;
    cudaGetSymbolAddress((void**)&pAhi,  gA_hi);
    cudaGetSymbolAddress((void**)&pAlo,  gA_lo);
    cudaGetSymbolAddress((void**)&pAOhi, gAO_hi);
    cudaGetSymbolAddress((void**)&pAOlo, gAO_lo);
    cudaGetSymbolAddress((void**)&pBqhi, gBq_hi);
    cudaGetSymbolAddress((void**)&pBqlo, gBq_lo);
    cudaGetSymbolAddress((void**)&pBohi, gBo_hi);
    cudaGetSymbolAddress((void**)&pBolo, gBo_lo);
    __half *hQh, *hQl, *hKh, *hKl, *hVh, *hVl;
    cudaGetSymbolAddress((void**)&hQh, gQh);
    cudaGetSymbolAddress((void**)&hQl, gQl);
    cudaGetSymbolAddress((void**)&hKh, gKh);
    cudaGetSymbolAddress((void**)&hKl, gKl);
    cudaGetSymbolAddress((void**)&hVh, gVh);
    cudaGetSymbolAddress((void**)&hVl, gVl);

    // 1) convert inputs (SW64 KC=32 blocked bf16 hi/lo)
    convA_kernel<<<4096, 256>>>(x, pAhi, pAlo);
    convB_kernel<<<dim3(NQKV / 256, KDIM / 8), 256>>>(Wqkv, NQKV, pBqhi, pBqlo);
    convB_kernel<<<dim3(CC / 256, KDIM / 8), 256>>>(Wout, CC, pBohi, pBolo);

    // 2) QKV projection (2 tiles/CTA, TMEM double-buffered)
    mm_kernel<0><<<dim3(NQKV / TN, BT / TM / MTILES), 160, MM_SMEM>>>(
        pAhi, pAlo, pBqhi, pBqlo, nullptr);

    // 3) flash attention v4 (reordered); emits bf16 hi/lo AO blocks
    flash_tc_kernel<<<dim3(16, BB * NH), 128, FTC_SMEM>>>(hQh, hQl, hKh, hKl, hVh, hVl);

    // 4) output projection (2 tiles/CTA)
    mm_kernel<1><<<dim3(CC / TN, BT / TM / MTILES), 160, MM_SMEM>>>(
        pAOhi, pAOlo, pBohi, pBolo, out);
}

// round 15
// speedup vs baseline: 1.5370x; 1.5370x over previous
#include <cuda_runtime.h>
#include <cuda_bf16.h>
#include <cuda_fp16.h>
#include <cstdint>

// Problem constants
#define BB 2
#define TT 2048
#define CC 2048
#define NH 16
#define DH 128
#define BT (BB * TT)        // 4096
#define NQKV (3 * CC)       // 6144
#define KDIM 2048
#define TM 128
#define TN 256

// KC=32 blocking (SW64) for the projection GEMMs
#define KC2 32
#define NKC2 (KDIM / KC2)   // 64
#define ABLK 8192           // 128*32*2 bytes
#define BBLK 16384          // 256*32*2 bytes
#define STG (2 * ABLK + 2 * BBLK)   // 49152
#define NSTAGE 4            // R6 config: 4-stage, 1 tile/CTA (proven best)

#if defined(__CUDA_ARCH_FEAT_SM103_ALL) || defined(__CUDA_ARCH_FEAT_SM100_ALL) || defined(__CUDA_ARCH_FEAT_SM101_ALL)
#define USE_TCGEN05 1
#else
#define USE_TCGEN05 0
#endif

// ---------------------------------------------------------------------------
// Scratch (device globals; allocation is forbidden)
// ---------------------------------------------------------------------------
__device__ __align__(128) __nv_bfloat16 gA_hi[BT * KDIM];
__device__ __align__(128) __nv_bfloat16 gA_lo[BT * KDIM];
__device__ __align__(128) __nv_bfloat16 gAO_hi[BT * KDIM];
__device__ __align__(128) __nv_bfloat16 gAO_lo[BT * KDIM];
__device__ __align__(128) __nv_bfloat16 gBq_hi[KDIM * NQKV];
__device__ __align__(128) __nv_bfloat16 gBq_lo[KDIM * NQKV];
__device__ __align__(128) __nv_bfloat16 gBo_hi[KDIM * CC];
__device__ __align__(128) __nv_bfloat16 gBo_lo[KDIM * CC];

// SW128 128x128 fp16 hi/lo attention tiles (32KB each tile)
__device__ __align__(128) __half gQh[BB * NH * TT * DH];
__device__ __align__(128) __half gQl[BB * NH * TT * DH];
__device__ __align__(128) __half gKh[BB * NH * TT * DH];
__device__ __align__(128) __half gKl[BB * NH * TT * DH];
__device__ __align__(128) __half gVh[BB * NH * TT * DH];   // V^T tiles
__device__ __align__(128) __half gVl[BB * NH * TT * DH];

// ---------------------------------------------------------------------------
// Helpers
// ---------------------------------------------------------------------------
#define SWZ128(o) ((o) ^ (((o) >> 3) & 0x70))
#define SWZ64(o)  ((o) ^ (((o) >> 3) & 0x30))

__device__ __forceinline__ uint32_t smem_u32(const void* p) {
    uint32_t a;
    asm("{ .reg .u64 t; cvta.to.shared.u64 t, %1; cvt.u32.u64 %0, t; }" : "=r"(a) : "l"(p));
    return a;
}

#if USE_TCGEN05
static constexpr uint64_t DESCB_SW128 =
    (uint64_t(2) << 61) | (uint64_t(1) << 46) | (uint64_t(64) << 32) | (uint64_t(1) << 16);
static constexpr uint64_t DESCB_SW64 =
    (uint64_t(4) << 61) | (uint64_t(1) << 46) | (uint64_t(32) << 32) | (uint64_t(1) << 16);
#define MAKE_DESC128(a) (DESCB_SW128 | ((uint64_t)((a) >> 4) & 0x3FFF))
#define MAKE_DESC64(a)  (DESCB_SW64  | ((uint64_t)((a) >> 4) & 0x3FFF))

__device__ __forceinline__ uint32_t elect1() {
    uint32_t p;
    asm volatile("{\n\t.reg .pred p;\n\telect.sync _|p, 0xFFFFFFFF;\n\tselp.b32 %0, 1, 0, p;\n\t}" : "=r"(p));
    return p;
}
__device__ __forceinline__ void mbar_init(uint32_t a, uint32_t c) {
    asm volatile("mbarrier.init.shared.b64 [%0], %1;" :: "r"(a), "r"(c) : "memory");
}
__device__ __forceinline__ void mbar_expect(uint32_t a, uint32_t tx) {
    asm volatile("mbarrier.arrive.expect_tx.shared.b64 _, [%0], %1;" :: "r"(a), "r"(tx) : "memory");
}
__device__ __forceinline__ void mbar_arrive(uint32_t a) {
    asm volatile("mbarrier.arrive.release.cta.shared.b64 _, [%0];" :: "r"(a) : "memory");
}
__device__ __forceinline__ void mbar_wait_acq(uint32_t a, uint32_t ph) {
    asm volatile(
        "{\n\t.reg .pred P;\n"
        "WL_%=:\n\t"
        "mbarrier.try_wait.parity.acquire.cta.shared::cta.b64 P, [%0], %1, 0x989680;\n\t"
        "@P bra WD_%=;\n\t"
        "bra WL_%=;\n"
        "WD_%=:\n\t}"
        :: "r"(a), "r"(ph) : "memory");
}
__device__ __forceinline__ void mbar_wait_rlx(uint32_t a, uint32_t ph) {
    asm volatile(
        "{\n\t.reg .pred P;\n"
        "WL_%=:\n\t"
        "mbarrier.try_wait.parity.relaxed.cta.shared::cta.b64 P, [%0], %1, 0x989680;\n\t"
        "@P bra WD_%=;\n\t"
        "bra WL_%=;\n"
        "WD_%=:\n\t}"
        :: "r"(a), "r"(ph) : "memory");
}
__device__ __forceinline__ void bulk_g2s(uint32_t dst, const void* src, uint32_t n, uint32_t mbar) {
    asm volatile(
        "cp.async.bulk.shared::cta.global.mbarrier::complete_tx::bytes [%0], [%1], %2, [%3];"
        :: "r"(dst), "l"(src), "r"(n), "r"(mbar) : "memory");
}
__device__ __forceinline__ void tc_alloc(uint32_t smem_res, uint32_t ncols) {
    asm volatile("tcgen05.alloc.cta_group::1.sync.aligned.shared::cta.b32 [%0], %1;"
                 :: "r"(smem_res), "r"(ncols) : "memory");
}
__device__ __forceinline__ void tc_dealloc(uint32_t tmem, uint32_t ncols) {
    asm volatile("tcgen05.dealloc.cta_group::1.sync.aligned.b32 %0, %1;" :: "r"(tmem), "r"(ncols));
}
__device__ __forceinline__ void tc_relinq() {
    asm volatile("tcgen05.relinquish_alloc_permit.cta_group::1.sync.aligned;");
}
__device__ __forceinline__ void tc_commit(uint32_t mbar) {
    asm volatile("tcgen05.commit.cta_group::1.mbarrier::arrive::one.shared::cluster.b64 [%0];"
                 :: "r"(mbar) : "memory");
}
__device__ __forceinline__ void tc_fence_before() {
    asm volatile("tcgen05.fence::before_thread_sync;" ::: "memory");
}
__device__ __forceinline__ void tc_fence_after() {
    asm volatile("tcgen05.fence::after_thread_sync;" ::: "memory");
}
__device__ __forceinline__ void tc_wait_ld() {
    asm volatile("tcgen05.wait::ld.sync.aligned;" ::: "memory");
}
__device__ __forceinline__ void tc_wait_st() {
    asm volatile("tcgen05.wait::st.sync.aligned;" ::: "memory");
}
__device__ __forceinline__ void mma_f16_ss(uint32_t d, uint64_t a, uint64_t b, uint32_t idesc, uint32_t en) {
    asm volatile(
        "{\n\t.reg .pred p;\n\t"
        "setp.ne.u32 p, %5, 0;\n\t"
        "tcgen05.mma.cta_group::1.kind::f16 [%0], %1, %2, %3, {%4, %4, %4, %4}, p;\n\t}"
        :: "r"(d), "l"(a), "l"(b), "r"(idesc), "r"(0u), "r"(en) : "memory");
}
__device__ __forceinline__ void mma_f16_ts(uint32_t d, uint32_t a, uint64_t b, uint32_t idesc, uint32_t en) {
    asm volatile(
        "{\n\t.reg .pred p;\n\t"
        "setp.ne.u32 p, %5, 0;\n\t"
        "tcgen05.mma.cta_group::1.kind::f16 [%0], [%1], %2, %3, {%4, %4, %4, %4}, p;\n\t}"
        :: "r"(d), "r"(a), "l"(b), "r"(idesc), "r"(0u), "r"(en) : "memory");
}
#define TC_LD_32X32B_X32(r, tmem_addr) \
    asm volatile( \
        "tcgen05.ld.sync.aligned.32x32b.x32.b32 " \
        "{%0, %1, %2, %3, %4, %5, %6, %7, " \
        " %8, %9, %10, %11, %12, %13, %14, %15, " \
        " %16, %17, %18, %19, %20, %21, %22, %23, " \
        " %24, %25, %26, %27, %28, %29, %30, %31}, [%32];" \
        : "=r"((r)[0]),  "=r"((r)[1]),  "=r"((r)[2]),  "=r"((r)[3]), \
          "=r"((r)[4]),  "=r"((r)[5]),  "=r"((r)[6]),  "=r"((r)[7]), \
          "=r"((r)[8]),  "=r"((r)[9]),  "=r"((r)[10]), "=r"((r)[11]), \
          "=r"((r)[12]), "=r"((r)[13]), "=r"((r)[14]), "=r"((r)[15]), \
          "=r"((r)[16]), "=r"((r)[17]), "=r"((r)[18]), "=r"((r)[19]), \
          "=r"((r)[20]), "=r"((r)[21]), "=r"((r)[22]), "=r"((r)[23]), \
          "=r"((r)[24]), "=r"((r)[25]), "=r"((r)[26]), "=r"((r)[27]), \
          "=r"((r)[28]), "=r"((r)[29]), "=r"((r)[30]), "=r"((r)[31]) \
        : "r"(tmem_addr))
#define TC_ST_32X32B_X32(tmem_addr, r) \
    asm volatile( \
        "tcgen05.st.sync.aligned.32x32b.x32.b32 [%0], " \
        "{%1, %2, %3, %4, %5, %6, %7, %8, " \
        " %9, %10, %11, %12, %13, %14, %15, %16, " \
        " %17, %18, %19, %20, %21, %22, %23, %24, " \
        " %25, %26, %27, %28, %29, %30, %31, %32};" \
        :: "r"(tmem_addr), \
           "r"((r)[0]),  "r"((r)[1]),  "r"((r)[2]),  "r"((r)[3]), \
           "r"((r)[4]),  "r"((r)[5]),  "r"((r)[6]),  "r"((r)[7]), \
           "r"((r)[8]),  "r"((r)[9]),  "r"((r)[10]), "r"((r)[11]), \
           "r"((r)[12]), "r"((r)[13]), "r"((r)[14]), "r"((r)[15]), \
           "r"((r)[16]), "r"((r)[17]), "r"((r)[18]), "r"((r)[19]), \
           "r"((r)[20]), "r"((r)[21]), "r"((r)[22]), "r"((r)[23]), \
           "r"((r)[24]), "r"((r)[25]), "r"((r)[26]), "r"((r)[27]), \
           "r"((r)[28]), "r"((r)[29]), "r"((r)[30]), "r"((r)[31]) \
        : "memory")

#define MM_IDESC ((1u<<4) | (1u<<7) | (1u<<10) | (32u<<17) | (8u<<24))
#define FA_IDESC ((1u<<4) | (16u<<17) | (8u<<24))
#endif // USE_TCGEN05

// ---------------------------------------------------------------------------
// Conversion kernels: fp32 -> SW64 KC=32-blocked bf16 hi/lo.
// ---------------------------------------------------------------------------
__global__ __launch_bounds__(256) void convA_kernel(
    const float* __restrict__ src, __nv_bfloat16* __restrict__ hi, __nv_bfloat16* __restrict__ lo)
{
    int e = blockIdx.x * 256 + threadIdx.x;
    int m = e >> 8;
    int k = (e & 255) << 3;
    float v[8];
    *(float4*)&v[0] = *(const float4*)&src[(size_t)m * KDIM + k];
    *(float4*)&v[4] = *(const float4*)&src[(size_t)m * KDIM + k + 4];
    __nv_bfloat16 hb[8], lb[8];
#pragma unroll
    for (int i = 0; i < 8; i++) {
        hb[i] = __float2bfloat16(v[i]);
        lb[i] = __float2bfloat16(v[i] - __bfloat162float(hb[i]));
    }
    int mt = m >> 7, r = m & 127, kc = k >> 5, kcol = k & 31;
    size_t blk = (size_t)(mt * NKC2 + kc) * ABLK;
    uint32_t off = SWZ64((uint32_t)(r * 64 + kcol * 2));
    *(uint4*)((char*)hi + blk + off) = *(uint4*)hb;
    *(uint4*)((char*)lo + blk + off) = *(uint4*)lb;
}

__global__ __launch_bounds__(256) void convB_kernel(
    const float* __restrict__ W, int N,
    __nv_bfloat16* __restrict__ hi, __nv_bfloat16* __restrict__ lo)
{
    int n = blockIdx.x * 256 + threadIdx.x;
    int k = blockIdx.y * 8;
    float v[8];
#pragma unroll
    for (int i = 0; i < 8; i++) v[i] = W[(size_t)(k + i) * N + n];
    __nv_bfloat16 hb[8], lb[8];
#pragma unroll
    for (int i = 0; i < 8; i++) {
        hb[i] = __float2bfloat16(v[i]);
        lb[i] = __float2bfloat16(v[i] - __bfloat162float(hb[i]));
    }
    int nt = n >> 8, nr = n & 255, kc = k >> 5, kcol = k & 31;
    size_t blk = (size_t)(nt * NKC2 + kc) * BBLK;
    uint32_t off = SWZ64((uint32_t)(nr * 64 + kcol * 2));
    *(uint4*)((char*)hi + blk + off) = *(uint4*)hb;
    *(uint4*)((char*)lo + blk + off) = *(uint4*)lb;
}

// ---------------------------------------------------------------------------
// tcgen05 GEMM: 128x256 tile/CTA, KC=32 SW64, 4-stage pipeline (R6/R13 exact).
// MODE 0: QKV -> fp16 hi/lo SW128 attention tiles.  MODE 1: fp32 row-major.
// ---------------------------------------------------------------------------
#define MM_SMEM (1024 + NSTAGE * STG)

template <int MODE>
__global__ __launch_bounds__(128) void mm_kernel(
    const __nv_bfloat16* __restrict__ Ahi, const __nv_bfloat16* __restrict__ Alo,
    const __nv_bfloat16* __restrict__ Bhi, const __nv_bfloat16* __restrict__ Blo,
    float* __restrict__ Cout)
{
    extern __shared__ char smem[];
    const int tid = threadIdx.x;
    const int nt = blockIdx.x, mt = blockIdx.y;

#if USE_TCGEN05
    __shared__ __align__(8) uint64_t s_ctrl[16];
    const uint32_t TMP = smem_u32(&s_ctrl[0]);
    uint32_t ful[NSTAGE], don[NSTAGE];
#pragma unroll
    for (int s = 0; s < NSTAGE; s++) {
        ful[s] = smem_u32(&s_ctrl[1 + s]);
        don[s] = smem_u32(&s_ctrl[1 + NSTAGE + s]);
    }
    const uint32_t FIN = smem_u32(&s_ctrl[1 + 2 * NSTAGE]);

    const uint32_t sb = smem_u32(smem);
    const uint32_t ab = (sb + 1023u) & ~1023u;
    char* smA = smem + (ab - sb);
    const int wid = tid >> 5, lane = tid & 31;

    if (wid == 0) { tc_alloc(TMP, 256); tc_relinq(); }
    if (tid == 0) {
#pragma unroll
        for (int s = 0; s < NSTAGE; s++) { mbar_init(ful[s], 1); mbar_init(don[s], 1); }
        mbar_init(FIN, 1);
    }
    __syncthreads();
    uint32_t tmem;
    asm volatile("ld.shared.b32 %0, [%1];" : "=r"(tmem) : "r"(TMP));

    const char* aB = (const char*)Ahi + (size_t)mt * NKC2 * ABLK;
    const char* aL = (const char*)Alo + (size_t)mt * NKC2 * ABLK;
    const char* bB = (const char*)Bhi + (size_t)nt * NKC2 * BBLK;
    const char* bL = (const char*)Blo + (size_t)nt * NKC2 * BBLK;

    if (wid == 0) {
        const uint32_t ep = elect1();
        int fph[NSTAGE], dph[NSTAGE];
#pragma unroll
        for (int s = 0; s < NSTAGE; s++) { fph[s] = 0; dph[s] = 0; }

        if (ep) {
#pragma unroll
            for (int s = 0; s < NSTAGE; s++) {
                uint32_t st = ab + s * STG;
                mbar_expect(ful[s], STG);
                bulk_g2s(st,             aB + (size_t)s * ABLK, ABLK, ful[s]);
                bulk_g2s(st + ABLK,      aL + (size_t)s * ABLK, ABLK, ful[s]);
                bulk_g2s(st + 2 * ABLK,  bB + (size_t)s * BBLK, BBLK, ful[s]);
                bulk_g2s(st + 2 * ABLK + BBLK, bL + (size_t)s * BBLK, BBLK, ful[s]);
            }
        }
        for (int kc = 0; kc < NKC2; kc++) {
            int st = kc & (NSTAGE - 1);
            uint32_t sbase = ab + st * STG;
            mbar_wait_rlx(ful[st], fph[st]); fph[st] ^= 1;
            if (ep) {
                uint64_t ah = MAKE_DESC64(sbase);
                uint64_t al = MAKE_DESC64(sbase + ABLK);
                uint64_t bh = MAKE_DESC64(sbase + 2 * ABLK);
                uint64_t bl = MAKE_DESC64(sbase + 2 * ABLK + BBLK);
#pragma unroll
                for (int ks = 0; ks < 2; ks++) {
                    uint64_t o = (uint64_t)(ks * 2);
                    uint32_t first = (kc == 0 && ks == 0) ? 0u : 1u;
                    mma_f16_ss(tmem, ah + o, bh + o, MM_IDESC, first);
                    mma_f16_ss(tmem, ah + o, bl + o, MM_IDESC, 1u);
                    mma_f16_ss(tmem, al + o, bh + o, MM_IDESC, 1u);
                }
                tc_commit(don[st]);
            }
            int pv = kc - 1;
            if (pv >= 0 && pv + NSTAGE < NKC2) {
                int ps = pv & (NSTAGE - 1);
                mbar_wait_rlx(don[ps], dph[ps]); dph[ps] ^= 1;
                if (ep) {
                    size_t nk = (size_t)(pv + NSTAGE);
                    uint32_t pb = ab + ps * STG;
                    mbar_expect(ful[ps], STG);
                    bulk_g2s(pb,             aB + nk * ABLK, ABLK, ful[ps]);
                    bulk_g2s(pb + ABLK,      aL + nk * ABLK, ABLK, ful[ps]);
                    bulk_g2s(pb + 2 * ABLK,  bB + nk * BBLK, BBLK, ful[ps]);
                    bulk_g2s(pb + 2 * ABLK + BBLK, bL + nk * BBLK, BBLK, ful[ps]);
                }
            }
        }
#pragma unroll
        for (int s = 0; s < NSTAGE; s++) { mbar_wait_rlx(don[s], dph[s]); }
        if (ep) mbar_arrive(FIN);
    }

    mbar_wait_acq(FIN, 0);
    tc_fence_after();

    // -------------------- epilogue --------------------
    const int mBase = mt * TM + wid * 32;
    const int nBase = nt * TN;
    float* sbuf = (float*)smA + wid * (32 * 33);

    if (MODE == 0) {
        const int b = mBase >> 11;
        const int tile = (mBase & 2047) >> 7;
        const int r0 = mBase & 127;
        const int which = nBase >> 11;
        const int h0 = (nBase & 2047) >> 7;
        const float qscale = 0.08838834764831845f;

#pragma unroll 1
        for (int ch = 0; ch < 8; ch++) {
            uint32_t rg[32];
            TC_LD_32X32B_X32(rg, tmem + ch * 32);
            tc_wait_ld();
            const int h = h0 + (ch >> 2);
            const int d0 = (ch & 3) * 32;
            const size_t tbase = ((size_t)(b * NH + h) * 16 + tile) * 32768;

            if (which != 2) {
                const float sc = (which == 0) ? qscale : 1.0f;
                __half hb[32], lb[32];
#pragma unroll
                for (int c = 0; c < 32; c++) {
                    float f = __uint_as_float(rg[c]) * sc;
                    __half hh = __float2half_rn(f);
                    hb[c] = hh;
                    lb[c] = __float2half_rn(f - __half2float(hh));
                }
                const int r = r0 + lane;
                const int atom = (r >> 3) + (d0 >> 6) * 16;
                const uint32_t base = (uint32_t)(atom * 1024 + (r & 7) * 128 + (d0 & 63) * 2);
                char* dh = (char*)((which == 0) ? gQh : gKh) + tbase;
                char* dl = (char*)((which == 0) ? gQl : gKl) + tbase;
#pragma unroll
                for (int q = 0; q < 4; q++) {
                    uint32_t o = SWZ128(base + q * 16);
                    *(uint4*)(dh + o) = ((uint4*)hb)[q];
                    *(uint4*)(dl + o) = ((uint4*)lb)[q];
                }
            } else {
#pragma unroll
                for (int c = 0; c < 32; c++) sbuf[lane * 33 + c] = __uint_as_float(rg[c]);
                __syncwarp();
                const int d = d0 + lane;
                const int ac2 = wid >> 1;
                const int ic2 = (wid & 1) * 32;
                const int atom2 = (d >> 3) + ac2 * 16;
                const uint32_t base2 = (uint32_t)(atom2 * 1024 + (d & 7) * 128 + ic2 * 2);
                __half hv[32], lv[32];
#pragma unroll
                for (int rr = 0; rr < 32; rr++) {
                    float f = sbuf[rr * 33 + lane];
                    __half hh = __float2half_rn(f);
                    hv[rr] = hh;
                    lv[rr] = __float2half_rn(f - __half2float(hh));
                }
#pragma unroll
                for (int q = 0; q < 4; q++) {
                    uint32_t o = SWZ128(base2 + q * 16);
                    *(uint4*)((char*)gVh + tbase + o) = ((uint4*)hv)[q];
                    *(uint4*)((char*)gVl + tbase + o) = ((uint4*)lv)[q];
                }
                __syncwarp();
            }
        }
    } else {
#pragma unroll 1
        for (int ch = 0; ch < 8; ch++) {
            uint32_t rg[32];
            TC_LD_32X32B_X32(rg, tmem + ch * 32);
            tc_wait_ld();
#pragma unroll
            for (int c = 0; c < 32; c++) sbuf[lane * 33 + c] = __uint_as_float(rg[c]);
            __syncwarp();
            int ncol0 = nBase + ch * 32;
#pragma unroll 4
            for (int rr = 0; rr < 32; rr++) {
                int m = mBase + rr;
                Cout[(size_t)m * CC + ncol0 + lane] = sbuf[rr * 33 + lane];
            }
            __syncwarp();
        }
    }
    __syncthreads();
    if (wid == 0) tc_dealloc(tmem, 256);
#endif
}

// ---------------------------------------------------------------------------
// tcgen05 flash attention v4: double-buffered S + reordered loop (softmax and
// P-store before the PD wait, so the PV tail overlaps independent work).
// TMEM: S0[0..127] S1[128..255] O[256..383] Qh[384..447] Ql[448..511].
// smem: K0h K0l K1h K1l Vh Vl (6 x 32KB).
// ---------------------------------------------------------------------------
#define FTC_SMEM (1024 + 6 * 32768)

__global__ __launch_bounds__(128, 1) void flash_tc_kernel(
    const __half* __restrict__ pQh, const __half* __restrict__ pQl,
    const __half* __restrict__ pKh, const __half* __restrict__ pKl,
    const __half* __restrict__ pVh, const __half* __restrict__ pVl)
{
#if USE_TCGEN05
    extern __shared__ char smem[];
    __shared__ __align__(8) uint64_t ctrl[8];
    const uint32_t TMP = smem_u32(&ctrl[0]);
    const uint32_t QF  = smem_u32(&ctrl[1]);
    const uint32_t KB0 = smem_u32(&ctrl[2]);
    const uint32_t KB1 = smem_u32(&ctrl[3]);
    const uint32_t VF  = smem_u32(&ctrl[4]);
    const uint32_t SD0 = smem_u32(&ctrl[5]);
    const uint32_t SD1 = smem_u32(&ctrl[6]);
    const uint32_t PD  = smem_u32(&ctrl[7]);
    const uint32_t KF[2] = { KB0, KB1 };
    const uint32_t SD[2] = { SD0, SD1 };

    const int tid = threadIdx.x, wid = tid >> 5, lane = tid & 31;
    const int bh = blockIdx.y;
    const int qt = (int)gridDim.x - 1 - (int)blockIdx.x;   // long CTAs first

    const uint32_t sb = smem_u32(smem);
    const uint32_t ab = (sb + 1023u) & ~1023u;
    char* smA = smem + (ab - sb);
    const uint32_t sKh[2] = { ab, ab + 65536 };
    const uint32_t sKl[2] = { ab + 32768, ab + 98304 };
    const uint32_t sVh = ab + 131072, sVl = ab + 163840;

    if (wid == 0) { tc_alloc(TMP, 512); tc_relinq(); }
    if (tid == 0) {
        mbar_init(QF, 1); mbar_init(KB0, 1); mbar_init(KB1, 1);
        mbar_init(VF, 1); mbar_init(SD0, 1); mbar_init(SD1, 1); mbar_init(PD, 1);
    }
    __syncthreads();
    uint32_t tmem;
    asm volatile("ld.shared.b32 %0, [%1];" : "=r"(tmem) : "r"(TMP));
    const uint32_t tS[2] = { tmem, tmem + 128 };
    const uint32_t tO = tmem + 256;
    const uint32_t tQh = tmem + 384, tQl = tmem + 448;
    const uint32_t woff = (uint32_t)wid << 21;

    const size_t headBase = (size_t)bh * 16 * 16384;       // elements
    const size_t qOff = headBase + (size_t)qt * 16384;

    // ---- stage Q through the (not yet used) V buffers, then STTM to TMEM ----
    if (wid == 0 && elect1()) {
        mbar_expect(QF, 65536);
        bulk_g2s(sVh, pQh + qOff, 32768, QF);
        bulk_g2s(sVl, pQl + qOff, 32768, QF);
    }
    mbar_wait_acq(QF, 0);
    {
        const int r = wid * 32 + lane;
        const char* srcH = smA + 131072;
        const char* srcL = smA + 163840;
        uint32_t qr[32];
        const uint32_t rowOff = (uint32_t)((r >> 3) * 1024 + (r & 7) * 128);
#pragma unroll
        for (int i = 0; i < 8; i++)
            *(uint4*)&qr[i * 4] = *(const uint4*)(srcH + SWZ128(rowOff + i * 16));
        TC_ST_32X32B_X32(tQh + woff, qr);
#pragma unroll
        for (int i = 0; i < 8; i++)
            *(uint4*)&qr[i * 4] = *(const uint4*)(srcH + SWZ128(rowOff + 16384 + i * 16));
        TC_ST_32X32B_X32(tQh + woff + 32, qr);
#pragma unroll
        for (int i = 0; i < 8; i++)
            *(uint4*)&qr[i * 4] = *(const uint4*)(srcL + SWZ128(rowOff + i * 16));
        TC_ST_32X32B_X32(tQl + woff, qr);
#pragma unroll
        for (int i = 0; i < 8; i++)
            *(uint4*)&qr[i * 4] = *(const uint4*)(srcL + SWZ128(rowOff + 16384 + i * 16));
        TC_ST_32X32B_X32(tQl + woff + 32, qr);
        tc_wait_st();
    }
    tc_fence_before();
    __syncthreads();

    // ---- prologue: K0, V0, K1 loads; issue S-MMA(0) into S0 ----
    if (wid == 0 && elect1()) {
        tc_fence_after();
        mbar_expect(KF[0], 65536);
        bulk_g2s(sKh[0], pKh + headBase, 32768, KF[0]);
        bulk_g2s(sKl[0], pKl + headBase, 32768, KF[0]);
        mbar_expect(VF, 65536);
        bulk_g2s(sVh, pVh + headBase, 32768, VF);
        bulk_g2s(sVl, pVl + headBase, 32768, VF);
        if (qt >= 1) {
            mbar_expect(KF[1], 65536);
            bulk_g2s(sKh[1], pKh + headBase + 16384, 32768, KF[1]);
            bulk_g2s(sKl[1], pKl + headBase + 16384, 32768, KF[1]);
        }
        mbar_wait_rlx(KF[0], 0);
        uint64_t dKh = MAKE_DESC128(sKh[0]), dKl = MAKE_DESC128(sKl[0]);
#pragma unroll
        for (int ks = 0; ks < 8; ks++) {
            uint64_t o = (uint64_t)((ks & 3) * 2 + (ks >> 2) * 1024);
            mma_f16_ts(tS[0], tQh + ks * 8, dKh + o, FA_IDESC, ks == 0 ? 0u : 1u);
            mma_f16_ts(tS[0], tQh + ks * 8, dKl + o, FA_IDESC, 1u);
            mma_f16_ts(tS[0], tQl + ks * 8, dKh + o, FA_IDESC, 1u);
        }
        tc_commit(SD[0]);
    }

    const float NEG_INF = __int_as_float(0xff800000);
    float m = NEG_INF, l = 0.f;

    for (int j = 0; j <= qt; j++) {
        const int bs = j & 1;

        // S(j) ready -> registers
        mbar_wait_acq(SD[bs], (j >> 1) & 1);
        tc_fence_after();
        float s[128];
#pragma unroll
        for (int c4 = 0; c4 < 4; c4++)
            TC_LD_32X32B_X32(((uint32_t*)s) + c4 * 32, tS[bs] + woff + c4 * 32);
        tc_wait_ld();

        // ---- softmax immediately (independent of PD) ----
        if (j == qt) {
            int qrow = wid * 32 + lane;
#pragma unroll
            for (int c = 0; c < 128; c++)
                if (c > qrow) s[c] = NEG_INF;
        }
        float mx = m;
#pragma unroll
        for (int c = 0; c < 128; c++) mx = fmaxf(mx, s[c]);
        float alpha = __expf(m - mx);
        m = mx;
        float ls = 0.f;
#pragma unroll
        for (int c = 0; c < 128; c++) {
            float p = __expf(s[c] - mx);
            s[c] = p;
            ls += p;
        }
        l = l * alpha + ls;

        // ---- P -> fp16x2 -> tS[bs] cols 0..63 (no PD needed: PV(j-1) reads
        //      tS[bs^1], S-MMA(j+1) writes tS[bs^1]; our LDTM already done) ----
        {
            uint32_t pk[32];
#pragma unroll
            for (int c = 0; c < 32; c++) {
                __half2 h2 = __floats2half2_rn(s[2 * c], s[2 * c + 1]);
                pk[c] = *reinterpret_cast<uint32_t*>(&h2);
            }
            TC_ST_32X32B_X32(tS[bs] + woff, pk);
#pragma unroll
            for (int c = 0; c < 32; c++) {
                __half2 h2 = __floats2half2_rn(s[64 + 2 * c], s[64 + 2 * c + 1]);
                pk[c] = *reinterpret_cast<uint32_t*>(&h2);
            }
            TC_ST_32X32B_X32(tS[bs] + woff + 32, pk);
            tc_wait_st();
        }

        // ---- now require PV(j-1) done (V reuse, P(j-1) buf reuse, O rescale) ----
        if (j > 0) { mbar_wait_acq(PD, (j - 1) & 1); tc_fence_after(); }

        if (wid == 0 && elect1()) {
            if (j > 0) {            // V(j) reload
                mbar_expect(VF, 65536);
                bulk_g2s(sVh, pVh + headBase + (size_t)j * 16384, 32768, VF);
                bulk_g2s(sVl, pVl + headBase + (size_t)j * 16384, 32768, VF);
            }
            if (j + 2 <= qt) {      // K(j+2) prefetch
                mbar_expect(KF[bs], 65536);
                bulk_g2s(sKh[bs], pKh + headBase + (size_t)(j + 2) * 16384, 32768, KF[bs]);
                bulk_g2s(sKl[bs], pKl + headBase + (size_t)(j + 2) * 16384, 32768, KF[bs]);
            }
            if (j + 1 <= qt) {      // S-MMA(j+1) into the other S buffer
                mbar_wait_rlx(KF[bs ^ 1], ((j + 1) >> 1) & 1);
                uint64_t dKh = MAKE_DESC128(sKh[bs ^ 1]), dKl = MAKE_DESC128(sKl[bs ^ 1]);
#pragma unroll
                for (int ks = 0; ks < 8; ks++) {
                    uint64_t o = (uint64_t)((ks & 3) * 2 + (ks >> 2) * 1024);
                    mma_f16_ts(tS[bs ^ 1], tQh + ks * 8, dKh + o, FA_IDESC, ks == 0 ? 0u : 1u);
                    mma_f16_ts(tS[bs ^ 1], tQh + ks * 8, dKl + o, FA_IDESC, 1u);
                    mma_f16_ts(tS[bs ^ 1], tQl + ks * 8, dKh + o, FA_IDESC, 1u);
                }
                tc_commit(SD[bs ^ 1]);
            }
        }

        // ---- O rescale (needs PD; per-warp skip when all alpha==1) ----
        if (j > 0 && !__all_sync(0xffffffffu, alpha == 1.0f)) {
#pragma unroll 1
            for (int c4 = 0; c4 < 4; c4++) {
                uint32_t o[32];
                TC_LD_32X32B_X32(o, tO + woff + c4 * 32);
                tc_wait_ld();
#pragma unroll
                for (int c = 0; c < 32; c++)
                    o[c] = __float_as_uint(__uint_as_float(o[c]) * alpha);
                TC_ST_32X32B_X32(tO + woff + c4 * 32, o);
            }
            tc_wait_st();
        }
        tc_fence_before();
        __syncthreads();

        // ---- O += P * V^T (A = P in tS[bs]) ----
        if (wid == 0 && elect1()) {
            mbar_wait_rlx(VF, j & 1);
            tc_fence_after();
            uint64_t dVh = MAKE_DESC128(sVh), dVl = MAKE_DESC128(sVl);
#pragma unroll
            for (int ks = 0; ks < 8; ks++) {
                uint64_t o = (uint64_t)((ks & 3) * 2 + (ks >> 2) * 1024);
                mma_f16_ts(tO, tS[bs] + ks * 8, dVh + o, FA_IDESC, (j == 0 && ks == 0) ? 0u : 1u);
            }
#pragma unroll
            for (int ks = 0; ks < 8; ks++) {
                uint64_t o = (uint64_t)((ks & 3) * 2 + (ks >> 2) * 1024);
                mma_f16_ts(tO, tS[bs] + ks * 8, dVl + o, FA_IDESC, 1u);
            }
            tc_commit(PD);
        }
    }

    mbar_wait_acq(PD, qt & 1);
    tc_fence_after();

    // ---- epilogue: O/l -> SW64 KC=32-blocked bf16 hi/lo AO ----
    const float invl = 1.0f / l;
    const int b = bh >> 4, h = bh & 15;
    const int r = wid * 32 + lane;
    const int mt2 = b * 16 + qt;
#pragma unroll 1
    for (int ch = 0; ch < 4; ch++) {
        uint32_t o[32];
        TC_LD_32X32B_X32(o, tO + woff + ch * 32);
        tc_wait_ld();
        __nv_bfloat16 hb[32], lb[32];
#pragma unroll
        for (int c = 0; c < 32; c++) {
            float f = __uint_as_float(o[c]) * invl;
            __nv_bfloat16 hh = __float2bfloat16(f);
            hb[c] = hh;
            lb[c] = __float2bfloat16(f - __bfloat162float(hh));
        }
        const int kc = h * 4 + ch;
        const size_t blk = (size_t)(mt2 * NKC2 + kc) * ABLK;
        const uint32_t base = (uint32_t)(r * 64);
#pragma unroll
        for (int q = 0; q < 4; q++) {
            uint32_t off = SWZ64(base + q * 16);
            *(uint4*)((char*)gAO_hi + blk + off) = ((uint4*)hb)[q];
            *(uint4*)((char*)gAO_lo + blk + off) = ((uint4*)lb)[q];
        }
    }
    __syncthreads();
    if (wid == 0) tc_dealloc(tmem, 512);
#endif
}

// ---------------------------------------------------------------------------
extern "C" void kernel_launch(void* const* d_in, const int* in_sizes, int n_in,
                              void* d_out, int out_size)
{
    const float* x    = (const float*)d_in[0];
    const float* Wqkv = (const float*)d_in[2];
    const float* Wout = (const float*)d_in[3];
    float* out = (float*)d_out;

    cudaFuncSetAttribute(mm_kernel<0>, cudaFuncAttributeMaxDynamicSharedMemorySize, MM_SMEM);
    cudaFuncSetAttribute(mm_kernel<1>, cudaFuncAttributeMaxDynamicSharedMemorySize, MM_SMEM);
    cudaFuncSetAttribute(flash_tc_kernel, cudaFuncAttributeMaxDynamicSharedMemorySize, FTC_SMEM);

    __nv_bfloat16 *pAhi, *pAlo, *pAOhi, *pAOlo, *pBqhi, *pBqlo, *pBohi, *pBolo;
    cudaGetSymbolAddress((void**)&pAhi,  gA_hi);
    cudaGetSymbolAddress((void**)&pAlo,  gA_lo);
    cudaGetSymbolAddress((void**)&pAOhi, gAO_hi);
    cudaGetSymbolAddress((void**)&pAOlo, gAO_lo);
    cudaGetSymbolAddress((void**)&pBqhi, gBq_hi);
    cudaGetSymbolAddress((void**)&pBqlo, gBq_lo);
    cudaGetSymbolAddress((void**)&pBohi, gBo_hi);
    cudaGetSymbolAddress((void**)&pBolo, gBo_lo);
    __half *hQh, *hQl, *hKh, *hKl, *hVh, *hVl;
    cudaGetSymbolAddress((void**)&hQh, gQh);
    cudaGetSymbolAddress((void**)&hQl, gQl);
    cudaGetSymbolAddress((void**)&hKh, gKh);
    cudaGetSymbolAddress((void**)&hKl, gKl);
    cudaGetSymbolAddress((void**)&hVh, gVh);
    cudaGetSymbolAddress((void**)&hVl, gVl);

    // 1) convert inputs (SW64 KC=32 blocked bf16 hi/lo)
    convA_kernel<<<4096, 256>>>(x, pAhi, pAlo);
    convB_kernel<<<dim3(NQKV / 256, KDIM / 8), 256>>>(Wqkv, NQKV, pBqhi, pBqlo);
    convB_kernel<<<dim3(CC / 256, KDIM / 8), 256>>>(Wout, CC, pBohi, pBolo);

    // 2) QKV projection (R6 config); emits fp16 hi/lo attention tiles
    mm_kernel<0><<<dim3(NQKV / TN, BT / TM), 128, MM_SMEM>>>(pAhi, pAlo, pBqhi, pBqlo, nullptr);

    // 3) flash attention v4 (reordered); emits bf16 hi/lo AO blocks
    flash_tc_kernel<<<dim3(16, BB * NH), 128, FTC_SMEM>>>(hQh, hQl, hKh, hKl, hVh, hVl);

    // 4) output projection (R6 config)
    mm_kernel<1><<<dim3(CC / TN, BT / TM), 128, MM_SMEM>>>(pAOhi, pAOlo, pBohi, pBolo, out);
}

// round 16
// speedup vs baseline: 1.6234x; 1.0562x over previous
#include <cuda_runtime.h>
#include <cuda_bf16.h>
#include <cuda_fp16.h>
#include <cstdint>

// Problem constants
#define BB 2
#define TT 2048
#define CC 2048
#define NH 16
#define DH 128
#define BT (BB * TT)        // 4096
#define NQKV (3 * CC)       // 6144
#define KDIM 2048
#define TM 128
#define TN 256

// KC=32 blocking (SW64) for the projection GEMMs
#define KC2 32
#define NKC2 (KDIM / KC2)   // 64
#define ABLK 8192           // 128*32*2 bytes
#define BBLK 16384          // 256*32*2 bytes
#define STG (2 * ABLK + 2 * BBLK)   // 49152
#define NSTAGE 4            // R6 config: 4-stage, 1 tile/CTA (proven best)

#if defined(__CUDA_ARCH_FEAT_SM103_ALL) || defined(__CUDA_ARCH_FEAT_SM100_ALL) || defined(__CUDA_ARCH_FEAT_SM101_ALL)
#define USE_TCGEN05 1
#else
#define USE_TCGEN05 0
#endif

// ---------------------------------------------------------------------------
// Scratch (device globals; allocation is forbidden)
// ---------------------------------------------------------------------------
__device__ __align__(128) __nv_bfloat16 gA_hi[BT * KDIM];
__device__ __align__(128) __nv_bfloat16 gA_lo[BT * KDIM];
__device__ __align__(128) __nv_bfloat16 gAO_hi[BT * KDIM];
__device__ __align__(128) __nv_bfloat16 gAO_lo[BT * KDIM];
__device__ __align__(128) __nv_bfloat16 gBq_hi[KDIM * NQKV];
__device__ __align__(128) __nv_bfloat16 gBq_lo[KDIM * NQKV];
__device__ __align__(128) __nv_bfloat16 gBo_hi[KDIM * CC];
__device__ __align__(128) __nv_bfloat16 gBo_lo[KDIM * CC];

// SW128 128x128 fp16 attention tiles (32KB each tile)
__device__ __align__(128) __half gQh[BB * NH * TT * DH];
__device__ __align__(128) __half gQl[BB * NH * TT * DH];
__device__ __align__(128) __half gKh[BB * NH * TT * DH];
__device__ __align__(128) __half gKl[BB * NH * TT * DH];
__device__ __align__(128) __half gVh[BB * NH * TT * DH];   // V^T tiles (single fp16)

// ---------------------------------------------------------------------------
// Helpers
// ---------------------------------------------------------------------------
#define SWZ128(o) ((o) ^ (((o) >> 3) & 0x70))
#define SWZ64(o)  ((o) ^ (((o) >> 3) & 0x30))

__device__ __forceinline__ uint32_t smem_u32(const void* p) {
    uint32_t a;
    asm("{ .reg .u64 t; cvta.to.shared.u64 t, %1; cvt.u32.u64 %0, t; }" : "=r"(a) : "l"(p));
    return a;
}

#if USE_TCGEN05
static constexpr uint64_t DESCB_SW128 =
    (uint64_t(2) << 61) | (uint64_t(1) << 46) | (uint64_t(64) << 32) | (uint64_t(1) << 16);
static constexpr uint64_t DESCB_SW64 =
    (uint64_t(4) << 61) | (uint64_t(1) << 46) | (uint64_t(32) << 32) | (uint64_t(1) << 16);
#define MAKE_DESC128(a) (DESCB_SW128 | ((uint64_t)((a) >> 4) & 0x3FFF))
#define MAKE_DESC64(a)  (DESCB_SW64  | ((uint64_t)((a) >> 4) & 0x3FFF))

__device__ __forceinline__ uint32_t elect1() {
    uint32_t p;
    asm volatile("{\n\t.reg .pred p;\n\telect.sync _|p, 0xFFFFFFFF;\n\tselp.b32 %0, 1, 0, p;\n\t}" : "=r"(p));
    return p;
}
__device__ __forceinline__ void mbar_init(uint32_t a, uint32_t c) {
    asm volatile("mbarrier.init.shared.b64 [%0], %1;" :: "r"(a), "r"(c) : "memory");
}
__device__ __forceinline__ void mbar_expect(uint32_t a, uint32_t tx) {
    asm volatile("mbarrier.arrive.expect_tx.shared.b64 _, [%0], %1;" :: "r"(a), "r"(tx) : "memory");
}
__device__ __forceinline__ void mbar_arrive(uint32_t a) {
    asm volatile("mbarrier.arrive.release.cta.shared.b64 _, [%0];" :: "r"(a) : "memory");
}
__device__ __forceinline__ void mbar_wait_acq(uint32_t a, uint32_t ph) {
    asm volatile(
        "{\n\t.reg .pred P;\n"
        "WL_%=:\n\t"
        "mbarrier.try_wait.parity.acquire.cta.shared::cta.b64 P, [%0], %1, 0x989680;\n\t"
        "@P bra WD_%=;\n\t"
        "bra WL_%=;\n"
        "WD_%=:\n\t}"
        :: "r"(a), "r"(ph) : "memory");
}
__device__ __forceinline__ void mbar_wait_rlx(uint32_t a, uint32_t ph) {
    asm volatile(
        "{\n\t.reg .pred P;\n"
        "WL_%=:\n\t"
        "mbarrier.try_wait.parity.relaxed.cta.shared::cta.b64 P, [%0], %1, 0x989680;\n\t"
        "@P bra WD_%=;\n\t"
        "bra WL_%=;\n"
        "WD_%=:\n\t}"
        :: "r"(a), "r"(ph) : "memory");
}
__device__ __forceinline__ void bulk_g2s(uint32_t dst, const void* src, uint32_t n, uint32_t mbar) {
    asm volatile(
        "cp.async.bulk.shared::cta.global.mbarrier::complete_tx::bytes [%0], [%1], %2, [%3];"
        :: "r"(dst), "l"(src), "r"(n), "r"(mbar) : "memory");
}
__device__ __forceinline__ void tc_alloc(uint32_t smem_res, uint32_t ncols) {
    asm volatile("tcgen05.alloc.cta_group::1.sync.aligned.shared::cta.b32 [%0], %1;"
                 :: "r"(smem_res), "r"(ncols) : "memory");
}
__device__ __forceinline__ void tc_dealloc(uint32_t tmem, uint32_t ncols) {
    asm volatile("tcgen05.dealloc.cta_group::1.sync.aligned.b32 %0, %1;" :: "r"(tmem), "r"(ncols));
}
__device__ __forceinline__ void tc_relinq() {
    asm volatile("tcgen05.relinquish_alloc_permit.cta_group::1.sync.aligned;");
}
__device__ __forceinline__ void tc_commit(uint32_t mbar) {
    asm volatile("tcgen05.commit.cta_group::1.mbarrier::arrive::one.shared::cluster.b64 [%0];"
                 :: "r"(mbar) : "memory");
}
__device__ __forceinline__ void tc_fence_before() {
    asm volatile("tcgen05.fence::before_thread_sync;" ::: "memory");
}
__device__ __forceinline__ void tc_fence_after() {
    asm volatile("tcgen05.fence::after_thread_sync;" ::: "memory");
}
__device__ __forceinline__ void tc_wait_ld() {
    asm volatile("tcgen05.wait::ld.sync.aligned;" ::: "memory");
}
__device__ __forceinline__ void tc_wait_st() {
    asm volatile("tcgen05.wait::st.sync.aligned;" ::: "memory");
}
__device__ __forceinline__ void mma_f16_ss(uint32_t d, uint64_t a, uint64_t b, uint32_t idesc, uint32_t en) {
    asm volatile(
        "{\n\t.reg .pred p;\n\t"
        "setp.ne.u32 p, %5, 0;\n\t"
        "tcgen05.mma.cta_group::1.kind::f16 [%0], %1, %2, %3, {%4, %4, %4, %4}, p;\n\t}"
        :: "r"(d), "l"(a), "l"(b), "r"(idesc), "r"(0u), "r"(en) : "memory");
}
__device__ __forceinline__ void mma_f16_ts(uint32_t d, uint32_t a, uint64_t b, uint32_t idesc, uint32_t en) {
    asm volatile(
        "{\n\t.reg .pred p;\n\t"
        "setp.ne.u32 p, %5, 0;\n\t"
        "tcgen05.mma.cta_group::1.kind::f16 [%0], [%1], %2, %3, {%4, %4, %4, %4}, p;\n\t}"
        :: "r"(d), "r"(a), "l"(b), "r"(idesc), "r"(0u), "r"(en) : "memory");
}
#define TC_LD_32X32B_X32(r, tmem_addr) \
    asm volatile( \
        "tcgen05.ld.sync.aligned.32x32b.x32.b32 " \
        "{%0, %1, %2, %3, %4, %5, %6, %7, " \
        " %8, %9, %10, %11, %12, %13, %14, %15, " \
        " %16, %17, %18, %19, %20, %21, %22, %23, " \
        " %24, %25, %26, %27, %28, %29, %30, %31}, [%32];" \
        : "=r"((r)[0]),  "=r"((r)[1]),  "=r"((r)[2]),  "=r"((r)[3]), \
          "=r"((r)[4]),  "=r"((r)[5]),  "=r"((r)[6]),  "=r"((r)[7]), \
          "=r"((r)[8]),  "=r"((r)[9]),  "=r"((r)[10]), "=r"((r)[11]), \
          "=r"((r)[12]), "=r"((r)[13]), "=r"((r)[14]), "=r"((r)[15]), \
          "=r"((r)[16]), "=r"((r)[17]), "=r"((r)[18]), "=r"((r)[19]), \
          "=r"((r)[20]), "=r"((r)[21]), "=r"((r)[22]), "=r"((r)[23]), \
          "=r"((r)[24]), "=r"((r)[25]), "=r"((r)[26]), "=r"((r)[27]), \
          "=r"((r)[28]), "=r"((r)[29]), "=r"((r)[30]), "=r"((r)[31]) \
        : "r"(tmem_addr))
#define TC_ST_32X32B_X32(tmem_addr, r) \
    asm volatile( \
        "tcgen05.st.sync.aligned.32x32b.x32.b32 [%0], " \
        "{%1, %2, %3, %4, %5, %6, %7, %8, " \
        " %9, %10, %11, %12, %13, %14, %15, %16, " \
        " %17, %18, %19, %20, %21, %22, %23, %24, " \
        " %25, %26, %27, %28, %29, %30, %31, %32};" \
        :: "r"(tmem_addr), \
           "r"((r)[0]),  "r"((r)[1]),  "r"((r)[2]),  "r"((r)[3]), \
           "r"((r)[4]),  "r"((r)[5]),  "r"((r)[6]),  "r"((r)[7]), \
           "r"((r)[8]),  "r"((r)[9]),  "r"((r)[10]), "r"((r)[11]), \
           "r"((r)[12]), "r"((r)[13]), "r"((r)[14]), "r"((r)[15]), \
           "r"((r)[16]), "r"((r)[17]), "r"((r)[18]), "r"((r)[19]), \
           "r"((r)[20]), "r"((r)[21]), "r"((r)[22]), "r"((r)[23]), \
           "r"((r)[24]), "r"((r)[25]), "r"((r)[26]), "r"((r)[27]), \
           "r"((r)[28]), "r"((r)[29]), "r"((r)[30]), "r"((r)[31]) \
        : "memory")

#define MM_IDESC ((1u<<4) | (1u<<7) | (1u<<10) | (32u<<17) | (8u<<24))
#define FA_IDESC ((1u<<4) | (16u<<17) | (8u<<24))
#endif // USE_TCGEN05

// ---------------------------------------------------------------------------
// Conversion kernels: fp32 -> SW64 KC=32-blocked bf16 hi/lo.
// ---------------------------------------------------------------------------
__global__ __launch_bounds__(256) void convA_kernel(
    const float* __restrict__ src, __nv_bfloat16* __restrict__ hi, __nv_bfloat16* __restrict__ lo)
{
    int e = blockIdx.x * 256 + threadIdx.x;
    int m = e >> 8;
    int k = (e & 255) << 3;
    float v[8];
    *(float4*)&v[0] = *(const float4*)&src[(size_t)m * KDIM + k];
    *(float4*)&v[4] = *(const float4*)&src[(size_t)m * KDIM + k + 4];
    __nv_bfloat16 hb[8], lb[8];
#pragma unroll
    for (int i = 0; i < 8; i++) {
        hb[i] = __float2bfloat16(v[i]);
        lb[i] = __float2bfloat16(v[i] - __bfloat162float(hb[i]));
    }
    int mt = m >> 7, r = m & 127, kc = k >> 5, kcol = k & 31;
    size_t blk = (size_t)(mt * NKC2 + kc) * ABLK;
    uint32_t off = SWZ64((uint32_t)(r * 64 + kcol * 2));
    *(uint4*)((char*)hi + blk + off) = *(uint4*)hb;
    *(uint4*)((char*)lo + blk + off) = *(uint4*)lb;
}

__global__ __launch_bounds__(256) void convB_kernel(
    const float* __restrict__ W, int N,
    __nv_bfloat16* __restrict__ hi, __nv_bfloat16* __restrict__ lo)
{
    int n = blockIdx.x * 256 + threadIdx.x;
    int k = blockIdx.y * 8;
    float v[8];
#pragma unroll
    for (int i = 0; i < 8; i++) v[i] = W[(size_t)(k + i) * N + n];
    __nv_bfloat16 hb[8], lb[8];
#pragma unroll
    for (int i = 0; i < 8; i++) {
        hb[i] = __float2bfloat16(v[i]);
        lb[i] = __float2bfloat16(v[i] - __bfloat162float(hb[i]));
    }
    int nt = n >> 8, nr = n & 255, kc = k >> 5, kcol = k & 31;
    size_t blk = (size_t)(nt * NKC2 + kc) * BBLK;
    uint32_t off = SWZ64((uint32_t)(nr * 64 + kcol * 2));
    *(uint4*)((char*)hi + blk + off) = *(uint4*)hb;
    *(uint4*)((char*)lo + blk + off) = *(uint4*)lb;
}

// ---------------------------------------------------------------------------
// tcgen05 GEMM: 128x256 tile/CTA, KC=32 SW64, 4-stage pipeline (R6/R13 exact).
// MODE 0: QKV -> fp16 attention tiles (Q/K hi+lo, V single).  MODE 1: fp32.
// ---------------------------------------------------------------------------
#define MM_SMEM (1024 + NSTAGE * STG)

template <int MODE>
__global__ __launch_bounds__(128) void mm_kernel(
    const __nv_bfloat16* __restrict__ Ahi, const __nv_bfloat16* __restrict__ Alo,
    const __nv_bfloat16* __restrict__ Bhi, const __nv_bfloat16* __restrict__ Blo,
    float* __restrict__ Cout)
{
    extern __shared__ char smem[];
    const int tid = threadIdx.x;
    const int nt = blockIdx.x, mt = blockIdx.y;

#if USE_TCGEN05
    __shared__ __align__(8) uint64_t s_ctrl[16];
    const uint32_t TMP = smem_u32(&s_ctrl[0]);
    uint32_t ful[NSTAGE], don[NSTAGE];
#pragma unroll
    for (int s = 0; s < NSTAGE; s++) {
        ful[s] = smem_u32(&s_ctrl[1 + s]);
        don[s] = smem_u32(&s_ctrl[1 + NSTAGE + s]);
    }
    const uint32_t FIN = smem_u32(&s_ctrl[1 + 2 * NSTAGE]);

    const uint32_t sb = smem_u32(smem);
    const uint32_t ab = (sb + 1023u) & ~1023u;
    char* smA = smem + (ab - sb);
    const int wid = tid >> 5, lane = tid & 31;

    if (wid == 0) { tc_alloc(TMP, 256); tc_relinq(); }
    if (tid == 0) {
#pragma unroll
        for (int s = 0; s < NSTAGE; s++) { mbar_init(ful[s], 1); mbar_init(don[s], 1); }
        mbar_init(FIN, 1);
    }
    __syncthreads();
    uint32_t tmem;
    asm volatile("ld.shared.b32 %0, [%1];" : "=r"(tmem) : "r"(TMP));

    const char* aB = (const char*)Ahi + (size_t)mt * NKC2 * ABLK;
    const char* aL = (const char*)Alo + (size_t)mt * NKC2 * ABLK;
    const char* bB = (const char*)Bhi + (size_t)nt * NKC2 * BBLK;
    const char* bL = (const char*)Blo + (size_t)nt * NKC2 * BBLK;

    if (wid == 0) {
        const uint32_t ep = elect1();
        int fph[NSTAGE], dph[NSTAGE];
#pragma unroll
        for (int s = 0; s < NSTAGE; s++) { fph[s] = 0; dph[s] = 0; }

        if (ep) {
#pragma unroll
            for (int s = 0; s < NSTAGE; s++) {
                uint32_t st = ab + s * STG;
                mbar_expect(ful[s], STG);
                bulk_g2s(st,             aB + (size_t)s * ABLK, ABLK, ful[s]);
                bulk_g2s(st + ABLK,      aL + (size_t)s * ABLK, ABLK, ful[s]);
                bulk_g2s(st + 2 * ABLK,  bB + (size_t)s * BBLK, BBLK, ful[s]);
                bulk_g2s(st + 2 * ABLK + BBLK, bL + (size_t)s * BBLK, BBLK, ful[s]);
            }
        }
        for (int kc = 0; kc < NKC2; kc++) {
            int st = kc & (NSTAGE - 1);
            uint32_t sbase = ab + st * STG;
            mbar_wait_rlx(ful[st], fph[st]); fph[st] ^= 1;
            if (ep) {
                uint64_t ah = MAKE_DESC64(sbase);
                uint64_t al = MAKE_DESC64(sbase + ABLK);
                uint64_t bh = MAKE_DESC64(sbase + 2 * ABLK);
                uint64_t bl = MAKE_DESC64(sbase + 2 * ABLK + BBLK);
#pragma unroll
                for (int ks = 0; ks < 2; ks++) {
                    uint64_t o = (uint64_t)(ks * 2);
                    uint32_t first = (kc == 0 && ks == 0) ? 0u : 1u;
                    mma_f16_ss(tmem, ah + o, bh + o, MM_IDESC, first);
                    mma_f16_ss(tmem, ah + o, bl + o, MM_IDESC, 1u);
                    mma_f16_ss(tmem, al + o, bh + o, MM_IDESC, 1u);
                }
                tc_commit(don[st]);
            }
            int pv = kc - 1;
            if (pv >= 0 && pv + NSTAGE < NKC2) {
                int ps = pv & (NSTAGE - 1);
                mbar_wait_rlx(don[ps], dph[ps]); dph[ps] ^= 1;
                if (ep) {
                    size_t nk = (size_t)(pv + NSTAGE);
                    uint32_t pb = ab + ps * STG;
                    mbar_expect(ful[ps], STG);
                    bulk_g2s(pb,             aB + nk * ABLK, ABLK, ful[ps]);
                    bulk_g2s(pb + ABLK,      aL + nk * ABLK, ABLK, ful[ps]);
                    bulk_g2s(pb + 2 * ABLK,  bB + nk * BBLK, BBLK, ful[ps]);
                    bulk_g2s(pb + 2 * ABLK + BBLK, bL + nk * BBLK, BBLK, ful[ps]);
                }
            }
        }
#pragma unroll
        for (int s = 0; s < NSTAGE; s++) { mbar_wait_rlx(don[s], dph[s]); }
        if (ep) mbar_arrive(FIN);
    }

    mbar_wait_acq(FIN, 0);
    tc_fence_after();

    // -------------------- epilogue --------------------
    const int mBase = mt * TM + wid * 32;
    const int nBase = nt * TN;
    float* sbuf = (float*)smA + wid * (32 * 33);

    if (MODE == 0) {
        const int b = mBase >> 11;
        const int tile = (mBase & 2047) >> 7;
        const int r0 = mBase & 127;
        const int which = nBase >> 11;
        const int h0 = (nBase & 2047) >> 7;
        const float qscale = 0.08838834764831845f;

#pragma unroll 1
        for (int ch = 0; ch < 8; ch++) {
            uint32_t rg[32];
            TC_LD_32X32B_X32(rg, tmem + ch * 32);
            tc_wait_ld();
            const int h = h0 + (ch >> 2);
            const int d0 = (ch & 3) * 32;
            const size_t tbase = ((size_t)(b * NH + h) * 16 + tile) * 32768;

            if (which != 2) {
                const float sc = (which == 0) ? qscale : 1.0f;
                __half hb[32], lb[32];
#pragma unroll
                for (int c = 0; c < 32; c++) {
                    float f = __uint_as_float(rg[c]) * sc;
                    __half hh = __float2half_rn(f);
                    hb[c] = hh;
                    lb[c] = __float2half_rn(f - __half2float(hh));
                }
                const int r = r0 + lane;
                const int atom = (r >> 3) + (d0 >> 6) * 16;
                const uint32_t base = (uint32_t)(atom * 1024 + (r & 7) * 128 + (d0 & 63) * 2);
                char* dh = (char*)((which == 0) ? gQh : gKh) + tbase;
                char* dl = (char*)((which == 0) ? gQl : gKl) + tbase;
#pragma unroll
                for (int q = 0; q < 4; q++) {
                    uint32_t o = SWZ128(base + q * 16);
                    *(uint4*)(dh + o) = ((uint4*)hb)[q];
                    *(uint4*)(dl + o) = ((uint4*)lb)[q];
                }
            } else {
                // V: single fp16, transpose via smem
#pragma unroll
                for (int c = 0; c < 32; c++) sbuf[lane * 33 + c] = __uint_as_float(rg[c]);
                __syncwarp();
                const int d = d0 + lane;
                const int ac2 = wid >> 1;
                const int ic2 = (wid & 1) * 32;
                const int atom2 = (d >> 3) + ac2 * 16;
                const uint32_t base2 = (uint32_t)(atom2 * 1024 + (d & 7) * 128 + ic2 * 2);
                __half hv[32];
#pragma unroll
                for (int rr = 0; rr < 32; rr++)
                    hv[rr] = __float2half_rn(sbuf[rr * 33 + lane]);
#pragma unroll
                for (int q = 0; q < 4; q++) {
                    uint32_t o = SWZ128(base2 + q * 16);
                    *(uint4*)((char*)gVh + tbase + o) = ((uint4*)hv)[q];
                }
                __syncwarp();
            }
        }
    } else {
#pragma unroll 1
        for (int ch = 0; ch < 8; ch++) {
            uint32_t rg[32];
            TC_LD_32X32B_X32(rg, tmem + ch * 32);
            tc_wait_ld();
#pragma unroll
            for (int c = 0; c < 32; c++) sbuf[lane * 33 + c] = __uint_as_float(rg[c]);
            __syncwarp();
            int ncol0 = nBase + ch * 32;
#pragma unroll 4
            for (int rr = 0; rr < 32; rr++) {
                int m = mBase + rr;
                Cout[(size_t)m * CC + ncol0 + lane] = sbuf[rr * 33 + lane];
            }
            __syncwarp();
        }
    }
    __syncthreads();
    if (wid == 0) tc_dealloc(tmem, 256);
#endif
}

// ---------------------------------------------------------------------------
// tcgen05 flash attention v5 (R13 v3 loop order): double-buffered S,
// single-fp16 V with double-buffered V smem (V load fully hidden),
// PV = 8 MMAs.
// TMEM: S0[0..127] S1[128..255] O[256..383] Qh[384..447] Ql[448..511].
// smem: K0h K0l K1h K1l V0 V1 (6 x 32KB).
// ---------------------------------------------------------------------------
#define FTC_SMEM (1024 + 6 * 32768)

__global__ __launch_bounds__(128, 1) void flash_tc_kernel(
    const __half* __restrict__ pQh, const __half* __restrict__ pQl,
    const __half* __restrict__ pKh, const __half* __restrict__ pKl,
    const __half* __restrict__ pV)
{
#if USE_TCGEN05
    extern __shared__ char smem[];
    __shared__ __align__(8) uint64_t ctrl[12];
    const uint32_t TMP = smem_u32(&ctrl[0]);
    const uint32_t QF  = smem_u32(&ctrl[1]);
    const uint32_t KF[2] = { smem_u32(&ctrl[2]), smem_u32(&ctrl[3]) };
    const uint32_t VB[2] = { smem_u32(&ctrl[4]), smem_u32(&ctrl[5]) };
    const uint32_t SD[2] = { smem_u32(&ctrl[6]), smem_u32(&ctrl[7]) };
    const uint32_t PD  = smem_u32(&ctrl[8]);

    const int tid = threadIdx.x, wid = tid >> 5, lane = tid & 31;
    const int bh = blockIdx.y;
    const int qt = (int)gridDim.x - 1 - (int)blockIdx.x;   // long CTAs first

    const uint32_t sb = smem_u32(smem);
    const uint32_t ab = (sb + 1023u) & ~1023u;
    char* smA = smem + (ab - sb);
    const uint32_t sKh[2] = { ab, ab + 65536 };
    const uint32_t sKl[2] = { ab + 32768, ab + 98304 };
    const uint32_t sV[2] = { ab + 131072, ab + 163840 };

    if (wid == 0) { tc_alloc(TMP, 512); tc_relinq(); }
    if (tid == 0) {
        mbar_init(QF, 1);
        mbar_init(KF[0], 1); mbar_init(KF[1], 1);
        mbar_init(VB[0], 1); mbar_init(VB[1], 1);
        mbar_init(SD[0], 1); mbar_init(SD[1], 1); mbar_init(PD, 1);
    }
    __syncthreads();
    uint32_t tmem;
    asm volatile("ld.shared.b32 %0, [%1];" : "=r"(tmem) : "r"(TMP));
    const uint32_t tS[2] = { tmem, tmem + 128 };
    const uint32_t tO = tmem + 256;
    const uint32_t tQh = tmem + 384, tQl = tmem + 448;
    const uint32_t woff = (uint32_t)wid << 21;

    const size_t headBase = (size_t)bh * 16 * 16384;       // elements
    const size_t qOff = headBase + (size_t)qt * 16384;

    // ---- stage Q through the (not yet used) V buffers, then STTM to TMEM ----
    if (wid == 0 && elect1()) {
        mbar_expect(QF, 65536);
        bulk_g2s(sV[0], pQh + qOff, 32768, QF);
        bulk_g2s(sV[1], pQl + qOff, 32768, QF);
    }
    mbar_wait_acq(QF, 0);
    {
        const int r = wid * 32 + lane;
        const char* srcH = smA + 131072;
        const char* srcL = smA + 163840;
        uint32_t qr[32];
        const uint32_t rowOff = (uint32_t)((r >> 3) * 1024 + (r & 7) * 128);
#pragma unroll
        for (int i = 0; i < 8; i++)
            *(uint4*)&qr[i * 4] = *(const uint4*)(srcH + SWZ128(rowOff + i * 16));
        TC_ST_32X32B_X32(tQh + woff, qr);
#pragma unroll
        for (int i = 0; i < 8; i++)
            *(uint4*)&qr[i * 4] = *(const uint4*)(srcH + SWZ128(rowOff + 16384 + i * 16));
        TC_ST_32X32B_X32(tQh + woff + 32, qr);
#pragma unroll
        for (int i = 0; i < 8; i++)
            *(uint4*)&qr[i * 4] = *(const uint4*)(srcL + SWZ128(rowOff + i * 16));
        TC_ST_32X32B_X32(tQl + woff, qr);
#pragma unroll
        for (int i = 0; i < 8; i++)
            *(uint4*)&qr[i * 4] = *(const uint4*)(srcL + SWZ128(rowOff + 16384 + i * 16));
        TC_ST_32X32B_X32(tQl + woff + 32, qr);
        tc_wait_st();
    }
    tc_fence_before();
    __syncthreads();

    // ---- prologue: K0, V0, K1, V1 loads; issue S-MMA(0) into S0 ----
    if (wid == 0 && elect1()) {
        tc_fence_after();
        mbar_expect(KF[0], 65536);
        bulk_g2s(sKh[0], pKh + headBase, 32768, KF[0]);
        bulk_g2s(sKl[0], pKl + headBase, 32768, KF[0]);
        mbar_expect(VB[0], 32768);
        bulk_g2s(sV[0], pV + headBase, 32768, VB[0]);
        if (qt >= 1) {
            mbar_expect(KF[1], 65536);
            bulk_g2s(sKh[1], pKh + headBase + 16384, 32768, KF[1]);
            bulk_g2s(sKl[1], pKl + headBase + 16384, 32768, KF[1]);
            mbar_expect(VB[1], 32768);
            bulk_g2s(sV[1], pV + headBase + 16384, 32768, VB[1]);
        }
        mbar_wait_rlx(KF[0], 0);
        uint64_t dKh = MAKE_DESC128(sKh[0]), dKl = MAKE_DESC128(sKl[0]);
#pragma unroll
        for (int ks = 0; ks < 8; ks++) {
            uint64_t o = (uint64_t)((ks & 3) * 2 + (ks >> 2) * 1024);
            mma_f16_ts(tS[0], tQh + ks * 8, dKh + o, FA_IDESC, ks == 0 ? 0u : 1u);
            mma_f16_ts(tS[0], tQh + ks * 8, dKl + o, FA_IDESC, 1u);
            mma_f16_ts(tS[0], tQl + ks * 8, dKh + o, FA_IDESC, 1u);
        }
        tc_commit(SD[0]);
    }

    const float NEG_INF = __int_as_float(0xff800000);
    float m = NEG_INF, l = 0.f;

    for (int j = 0; j <= qt; j++) {
        const int bs = j & 1;

        // S(j) ready -> registers
        mbar_wait_acq(SD[bs], (j >> 1) & 1);
        tc_fence_after();
        float s[128];
#pragma unroll
        for (int c4 = 0; c4 < 4; c4++)
            TC_LD_32X32B_X32(((uint32_t*)s) + c4 * 32, tS[bs] + woff + c4 * 32);
        tc_wait_ld();

        // PV(j-1) done? (orders P(j-1) buf reuse, O rescale, V(j+1) buf reuse)
        if (j > 0) { mbar_wait_acq(PD, (j - 1) & 1); tc_fence_after(); }

        if (wid == 0 && elect1()) {
            if (j > 0 && j + 1 <= qt) {   // V(j+1) load into sV[(j+1)&1]
                mbar_expect(VB[(j + 1) & 1], 32768);
                bulk_g2s(sV[(j + 1) & 1], pV + headBase + (size_t)(j + 1) * 16384,
                         32768, VB[(j + 1) & 1]);
            }
            if (j + 2 <= qt) {            // K(j+2) prefetch
                mbar_expect(KF[bs], 65536);
                bulk_g2s(sKh[bs], pKh + headBase + (size_t)(j + 2) * 16384, 32768, KF[bs]);
                bulk_g2s(sKl[bs], pKl + headBase + (size_t)(j + 2) * 16384, 32768, KF[bs]);
            }
            if (j + 1 <= qt) {            // S-MMA(j+1) into the other S buffer
                mbar_wait_rlx(KF[bs ^ 1], ((j + 1) >> 1) & 1);
                uint64_t dKh = MAKE_DESC128(sKh[bs ^ 1]), dKl = MAKE_DESC128(sKl[bs ^ 1]);
#pragma unroll
                for (int ks = 0; ks < 8; ks++) {
                    uint64_t o = (uint64_t)((ks & 3) * 2 + (ks >> 2) * 1024);
                    mma_f16_ts(tS[bs ^ 1], tQh + ks * 8, dKh + o, FA_IDESC, ks == 0 ? 0u : 1u);
                    mma_f16_ts(tS[bs ^ 1], tQh + ks * 8, dKl + o, FA_IDESC, 1u);
                    mma_f16_ts(tS[bs ^ 1], tQl + ks * 8, dKh + o, FA_IDESC, 1u);
                }
                tc_commit(SD[bs ^ 1]);
            }
        }

        // ---- softmax on registers (overlaps S-MMA(j+1)) ----
        if (j == qt) {
            int qrow = wid * 32 + lane;
#pragma unroll
            for (int c = 0; c < 128; c++)
                if (c > qrow) s[c] = NEG_INF;
        }
        float mx = m;
#pragma unroll
        for (int c = 0; c < 128; c++) mx = fmaxf(mx, s[c]);
        float alpha = __expf(m - mx);
        m = mx;
        float ls = 0.f;
#pragma unroll
        for (int c = 0; c < 128; c++) {
            float p = __expf(s[c] - mx);
            s[c] = p;
            ls += p;
        }
        l = l * alpha + ls;

        // ---- P -> fp16x2 -> tS[bs] cols 0..63 ----
        {
            uint32_t pk[32];
#pragma unroll
            for (int c = 0; c < 32; c++) {
                __half2 h2 = __floats2half2_rn(s[2 * c], s[2 * c + 1]);
                pk[c] = *reinterpret_cast<uint32_t*>(&h2);
            }
            TC_ST_32X32B_X32(tS[bs] + woff, pk);
#pragma unroll
            for (int c = 0; c < 32; c++) {
                __half2 h2 = __floats2half2_rn(s[64 + 2 * c], s[64 + 2 * c + 1]);
                pk[c] = *reinterpret_cast<uint32_t*>(&h2);
            }
            TC_ST_32X32B_X32(tS[bs] + woff + 32, pk);
            tc_wait_st();
        }

        // ---- O rescale (per-warp skip when all alpha==1) ----
        if (j > 0 && !__all_sync(0xffffffffu, alpha == 1.0f)) {
#pragma unroll 1
            for (int c4 = 0; c4 < 4; c4++) {
                uint32_t o[32];
                TC_LD_32X32B_X32(o, tO + woff + c4 * 32);
                tc_wait_ld();
#pragma unroll
                for (int c = 0; c < 32; c++)
                    o[c] = __float_as_uint(__uint_as_float(o[c]) * alpha);
                TC_ST_32X32B_X32(tO + woff + c4 * 32, o);
            }
            tc_wait_st();
        }
        tc_fence_before();
        __syncthreads();

        // ---- O += P * V^T (A = P in tS[bs], B = single-fp16 V) ----
        if (wid == 0 && elect1()) {
            mbar_wait_rlx(VB[bs], (j >> 1) & 1);
            tc_fence_after();
            uint64_t dV = MAKE_DESC128(sV[bs]);
#pragma unroll
            for (int ks = 0; ks < 8; ks++) {
                uint64_t o = (uint64_t)((ks & 3) * 2 + (ks >> 2) * 1024);
                mma_f16_ts(tO, tS[bs] + ks * 8, dV + o, FA_IDESC, (j == 0 && ks == 0) ? 0u : 1u);
            }
            tc_commit(PD);
        }
    }

    mbar_wait_acq(PD, qt & 1);
    tc_fence_after();

    // ---- epilogue: O/l -> SW64 KC=32-blocked bf16 hi/lo AO ----
    const float invl = 1.0f / l;
    const int b = bh >> 4, h = bh & 15;
    const int r = wid * 32 + lane;
    const int mt2 = b * 16 + qt;
#pragma unroll 1
    for (int ch = 0; ch < 4; ch++) {
        uint32_t o[32];
        TC_LD_32X32B_X32(o, tO + woff + ch * 32);
        tc_wait_ld();
        __nv_bfloat16 hb[32], lb[32];
#pragma unroll
        for (int c = 0; c < 32; c++) {
            float f = __uint_as_float(o[c]) * invl;
            __nv_bfloat16 hh = __float2bfloat16(f);
            hb[c] = hh;
            lb[c] = __float2bfloat16(f - __bfloat162float(hh));
        }
        const int kc = h * 4 + ch;
        const size_t blk = (size_t)(mt2 * NKC2 + kc) * ABLK;
        const uint32_t base = (uint32_t)(r * 64);
#pragma unroll
        for (int q = 0; q < 4; q++) {
            uint32_t off = SWZ64(base + q * 16);
            *(uint4*)((char*)gAO_hi + blk + off) = ((uint4*)hb)[q];
            *(uint4*)((char*)gAO_lo + blk + off) = ((uint4*)lb)[q];
        }
    }
    __syncthreads();
    if (wid == 0) tc_dealloc(tmem, 512);
#endif
}

// ---------------------------------------------------------------------------
extern "C" void kernel_launch(void* const* d_in, const int* in_sizes, int n_in,
                              void* d_out, int out_size)
{
    const float* x    = (const float*)d_in[0];
    const float* Wqkv = (const float*)d_in[2];
    const float* Wout = (const float*)d_in[3];
    float* out = (float*)d_out;

    cudaFuncSetAttribute(mm_kernel<0>, cudaFuncAttributeMaxDynamicSharedMemorySize, MM_SMEM);
    cudaFuncSetAttribute(mm_kernel<1>, cudaFuncAttributeMaxDynamicSharedMemorySize, MM_SMEM);
    cudaFuncSetAttribute(flash_tc_kernel, cudaFuncAttributeMaxDynamicSharedMemorySize, FTC_SMEM);

    __nv_bfloat16 *pAhi, *pAlo, *pAOhi, *pAOlo, *pBqhi, *pBqlo, *pBohi, *pBolo;
    cudaGetSymbolAddress((void**)&pAhi,  gA_hi);
    cudaGetSymbolAddress((void**)&pAlo,  gA_lo);
    cudaGetSymbolAddress((void**)&pAOhi, gAO_hi);
    cudaGetSymbolAddress((void**)&pAOlo, gAO_lo);
    cudaGetSymbolAddress((void**)&pBqhi, gBq_hi);
    cudaGetSymbolAddress((void**)&pBqlo, gBq_lo);
    cudaGetSymbolAddress((void**)&pBohi, gBo_hi);
    cudaGetSymbolAddress((void**)&pBolo, gBo_lo);
    __half *hQh, *hQl, *hKh, *hKl, *hVh;
    cudaGetSymbolAddress((void**)&hQh, gQh);
    cudaGetSymbolAddress((void**)&hQl, gQl);
    cudaGetSymbolAddress((void**)&hKh, gKh);
    cudaGetSymbolAddress((void**)&hKl, gKl);
    cudaGetSymbolAddress((void**)&hVh, gVh);

    // 1) convert inputs (SW64 KC=32 blocked bf16 hi/lo)
    convA_kernel<<<4096, 256>>>(x, pAhi, pAlo);
    convB_kernel<<<dim3(NQKV / 256, KDIM / 8), 256>>>(Wqkv, NQKV, pBqhi, pBqlo);
    convB_kernel<<<dim3(CC / 256, KDIM / 8), 256>>>(Wout, CC, pBohi, pBolo);

    // 2) QKV projection (R6 config); emits fp16 attention tiles
    mm_kernel<0><<<dim3(NQKV / TN, BT / TM), 128, MM_SMEM>>>(pAhi, pAlo, pBqhi, pBqlo, nullptr);

    // 3) flash attention v5 (single-fp16 V, double-buffered V)
    flash_tc_kernel<<<dim3(16, BB * NH), 128, FTC_SMEM>>>(hQh, hQl, hKh, hKl, hVh);

    // 4) output projection (R6 config)
    mm_kernel<1><<<dim3(CC / TN, BT / TM), 128, MM_SMEM>>>(pAOhi, pAOlo, pBohi, pBolo, out);
}